// round 1
// baseline (speedup 1.0000x reference)
#include <cuda_runtime.h>
#include <math.h>

// ---------------------------------------------------------------------------
// Problem constants
// ---------------------------------------------------------------------------
#define NTOK      49            // tokens per window
#define DIM       384
#define NHEADS    12
#define HD        32            // head dim
#define NWIN      4096          // total windows (B_)
#define NMASK     1024          // distinct masks (nW)
#define M_TOTAL   (NWIN * NTOK) // 200704 rows
#define QKV_N     (3 * DIM)     // 1152
#define ATTN_SCALE 0.17677669529663687f   // 32^-0.5

// Scratch (allocation-free rule: static __device__ arrays)
__device__ float g_qkv[(size_t)M_TOTAL * QKV_N];   // [M, 1152] = (w,i) x (m*384 + h*32 + d)
__device__ float g_att[(size_t)M_TOTAL * DIM];     // [M, 384]  = (w,i) x (h*32 + d)

// ---------------------------------------------------------------------------
// SGEMM:  C[M,N] = A[M,K] @ W[N,K]^T + bias[N]
// BM=BN=128, BK=8, 256 threads, 8x8 register tile per thread.
// M % 128 == 0, N % 128 == 0, K % 8 == 0 (all exact for this problem).
// ---------------------------------------------------------------------------
__global__ __launch_bounds__(256, 2)
void sgemm_bias_kernel(const float* __restrict__ A,
                       const float* __restrict__ W,
                       const float* __restrict__ bias,
                       float* __restrict__ C,
                       int N, int K) {
    constexpr int BM = 128, BN = 128, BK = 8, TM = 8, TN = 8;
    __shared__ float As[BK][BM];
    __shared__ float Bs[BK][BN];

    const int tid = threadIdx.x;
    const int mb  = blockIdx.y * BM;
    const int nb  = blockIdx.x * BN;

    // Loaders: 256 threads, each loads one float4 of A and one float4 of W per BK step
    const int rowA = tid >> 1;            // 0..127
    const int colA = (tid & 1) * 4;       // 0 or 4
    const int rowB = tid >> 1;
    const int colB = (tid & 1) * 4;

    const int tr = (tid / 16) * TM;       // row offset in tile
    const int tc = (tid % 16) * TN;       // col offset in tile

    const float* Aptr = A + (size_t)(mb + rowA) * K + colA;
    const float* Wptr = W + (size_t)(nb + rowB) * K + colB;

    float acc[TM][TN];
    #pragma unroll
    for (int i = 0; i < TM; i++)
        #pragma unroll
        for (int j = 0; j < TN; j++) acc[i][j] = 0.0f;

    for (int k0 = 0; k0 < K; k0 += BK) {
        float4 a4 = *reinterpret_cast<const float4*>(Aptr + k0);
        float4 b4 = *reinterpret_cast<const float4*>(Wptr + k0);
        As[colA + 0][rowA] = a4.x;
        As[colA + 1][rowA] = a4.y;
        As[colA + 2][rowA] = a4.z;
        As[colA + 3][rowA] = a4.w;
        Bs[colB + 0][rowB] = b4.x;
        Bs[colB + 1][rowB] = b4.y;
        Bs[colB + 2][rowB] = b4.z;
        Bs[colB + 3][rowB] = b4.w;
        __syncthreads();

        #pragma unroll
        for (int kk = 0; kk < BK; kk++) {
            float ar[TM], br[TN];
            #pragma unroll
            for (int i = 0; i < TM; i++) ar[i] = As[kk][tr + i];
            #pragma unroll
            for (int j = 0; j < TN; j++) br[j] = Bs[kk][tc + j];
            #pragma unroll
            for (int i = 0; i < TM; i++)
                #pragma unroll
                for (int j = 0; j < TN; j++)
                    acc[i][j] = fmaf(ar[i], br[j], acc[i][j]);
        }
        __syncthreads();
    }

    #pragma unroll
    for (int i = 0; i < TM; i++) {
        float* crow = C + (size_t)(mb + tr + i) * N + nb + tc;
        #pragma unroll
        for (int j = 0; j < TN; j++)
            crow[j] = acc[i][j] + bias[nb + tc + j];
    }
}

// ---------------------------------------------------------------------------
// Window attention: one CTA per (window, head).
//   scores = (q*scale) @ k^T + rpb[rel_idx][h] + mask[w % 1024]
//   P = softmax(scores); O = P @ v  -> g_att[(w*49+i)*384 + h*32 + d]
// ---------------------------------------------------------------------------
__global__ __launch_bounds__(256, 4)
void win_attn_kernel(const float* __restrict__ qkv,
                     const float* __restrict__ mask,
                     const float* __restrict__ rpb,
                     const int*   __restrict__ rel_idx,
                     float* __restrict__ attout) {
    const int w = blockIdx.x / NHEADS;
    const int h = blockIdx.x % NHEADS;
    const int tid = threadIdx.x;

    __shared__ float qs[NTOK][HD + 1];
    __shared__ float ks[NTOK][HD + 1];
    __shared__ float vs[NTOK][HD + 1];
    __shared__ float Ss[NTOK][NTOK + 1];

    // Stage q (pre-scaled), k, v
    const float* base = qkv + (size_t)w * NTOK * QKV_N + h * HD;
    for (int idx = tid; idx < NTOK * HD; idx += 256) {
        const int i = idx >> 5;
        const int d = idx & 31;
        const float* r = base + (size_t)i * QKV_N;
        qs[i][d] = r[d] * ATTN_SCALE;
        ks[i][d] = r[DIM + d];
        vs[i][d] = r[2 * DIM + d];
    }
    __syncthreads();

    // Scores + bias + mask
    const float* mrow = mask + (size_t)(w % NMASK) * NTOK * NTOK;
    for (int idx = tid; idx < NTOK * NTOK; idx += 256) {
        const int i = idx / NTOK;
        const int j = idx - i * NTOK;
        float s = 0.0f;
        #pragma unroll
        for (int d = 0; d < HD; d++)
            s = fmaf(qs[i][d], ks[j][d], s);
        s += rpb[rel_idx[idx] * NHEADS + h] + mrow[idx];
        Ss[i][j] = s;
    }
    __syncthreads();

    // Softmax: one warp per row (8 warps, rows strided by 8)
    const int warp = tid >> 5;
    const int lane = tid & 31;
    for (int r = warp; r < NTOK; r += 8) {
        float v0 = Ss[r][lane];
        const bool has2 = (lane + 32) < NTOK;
        float v1 = has2 ? Ss[r][lane + 32] : -1e30f;
        float m = fmaxf(v0, v1);
        #pragma unroll
        for (int off = 16; off; off >>= 1)
            m = fmaxf(m, __shfl_xor_sync(0xffffffffu, m, off));
        float e0 = __expf(v0 - m);
        float e1 = has2 ? __expf(v1 - m) : 0.0f;
        float sum = e0 + e1;
        #pragma unroll
        for (int off = 16; off; off >>= 1)
            sum += __shfl_xor_sync(0xffffffffu, sum, off);
        const float inv = 1.0f / sum;
        Ss[r][lane] = e0 * inv;
        if (has2) Ss[r][lane + 32] = e1 * inv;
    }
    __syncthreads();

    // O = P @ V, scatter into (B_, N, DIM) layout
    float* obase = attout + (size_t)w * NTOK * DIM + h * HD;
    for (int idx = tid; idx < NTOK * HD; idx += 256) {
        const int i = idx >> 5;
        const int d = idx & 31;
        float o = 0.0f;
        #pragma unroll
        for (int j = 0; j < NTOK; j++)
            o = fmaf(Ss[i][j], vs[j][d], o);
        obase[(size_t)i * DIM + d] = o;
    }
}

// ---------------------------------------------------------------------------
// Launch
// ---------------------------------------------------------------------------
extern "C" void kernel_launch(void* const* d_in, const int* in_sizes, int n_in,
                              void* d_out, int out_size) {
    const float* x      = (const float*)d_in[0];
    const float* mask   = (const float*)d_in[1];
    const float* rpb    = (const float*)d_in[2];
    const float* qkv_w  = (const float*)d_in[3];
    const float* qkv_b  = (const float*)d_in[4];
    const float* proj_w = (const float*)d_in[5];
    const float* proj_b = (const float*)d_in[6];
    const int*   rel_i  = (const int*)d_in[7];
    float* out = (float*)d_out;

    float* qkv_buf = nullptr;
    float* att_buf = nullptr;
    cudaGetSymbolAddress((void**)&qkv_buf, g_qkv);
    cudaGetSymbolAddress((void**)&att_buf, g_att);

    // 1) QKV projection: [200704, 384] @ [1152, 384]^T + b -> [200704, 1152]
    {
        dim3 grid(QKV_N / 128, M_TOTAL / 128);
        sgemm_bias_kernel<<<grid, 256>>>(x, qkv_w, qkv_b, qkv_buf, QKV_N, DIM);
    }

    // 2) Windowed attention per (window, head)
    {
        win_attn_kernel<<<NWIN * NHEADS, 256>>>(qkv_buf, mask, rpb, rel_i, att_buf);
    }

    // 3) Output projection: [200704, 384] @ [384, 384]^T + b -> d_out
    {
        dim3 grid(DIM / 128, M_TOTAL / 128);
        sgemm_bias_kernel<<<grid, 256>>>(att_buf, proj_w, proj_b, out, DIM, DIM);
    }
}

// round 3
// speedup vs baseline: 2.2197x; 2.2197x over previous
#include <cuda_runtime.h>
#include <cstdint>
#include <math.h>

// ---------------------------------------------------------------------------
// Problem constants
// ---------------------------------------------------------------------------
#define NTOK      49
#define DIM       384
#define NHEADS    12
#define HD        32
#define NWIN      4096
#define NMASK     1024
#define M_TOTAL   (NWIN * NTOK)     // 200704
#define QKV_N     (3 * DIM)         // 1152
#define KTOT      384
#define ATTN_SCALE 0.17677669529663687f

// Scratch (__device__ globals; allocation-free rule)
__device__ __align__(128) float g_qkv[(size_t)M_TOTAL * QKV_N];
__device__ __align__(128) float g_att[(size_t)M_TOTAL * DIM];   // rounded-x, then attn out
__device__ __align__(128) float g_wq[QKV_N * DIM];
__device__ __align__(128) float g_wp[DIM * DIM];

// ---------------------------------------------------------------------------
// Helpers
// ---------------------------------------------------------------------------
__device__ __forceinline__ uint32_t smem_u32(const void* p) {
    uint32_t a;
    asm("{ .reg .u64 t; cvta.to.shared.u64 t, %1; cvt.u32.u64 %0, t; }" : "=r"(a) : "l"(p));
    return a;
}

__device__ __forceinline__ void cpa16(uint32_t dst, const void* src) {
    asm volatile("cp.async.cg.shared.global [%0], [%1], 16;" :: "r"(dst), "l"(src) : "memory");
}
#define CP_COMMIT() asm volatile("cp.async.commit_group;" ::: "memory")
#define CP_WAIT1()  asm volatile("cp.async.wait_group 1;" ::: "memory")

__device__ __forceinline__ float tf32r(float f) {
    float r;
    asm("cvt.rna.tf32.f32 %0, %1;" : "=f"(r) : "f"(f));
    return r;
}

__device__ __forceinline__ void mma_tf32(float* d, const uint32_t* a, const uint32_t* b) {
    asm volatile(
        "mma.sync.aligned.m16n8k8.row.col.f32.tf32.tf32.f32 "
        "{%0,%1,%2,%3}, {%4,%5,%6,%7}, {%8,%9}, {%0,%1,%2,%3};"
        : "+f"(d[0]), "+f"(d[1]), "+f"(d[2]), "+f"(d[3])
        : "r"(a[0]), "r"(a[1]), "r"(a[2]), "r"(a[3]), "r"(b[0]), "r"(b[1]));
}

// ---------------------------------------------------------------------------
// Tensor-core tf32 GEMM via mma.sync:
//   C[M,Ntot] = A[M,384] @ W[Ntot,384]^T + bias
// BM=BN=128, BK=16, 3-stage cp.async pipeline, 8 warps x (64x32) warp tiles.
// Inputs must already be tf32-rounded. All tile dims divide exactly.
// ---------------------------------------------------------------------------
#define BK       16
#define NSTAGE   3
#define KITERS   (KTOT / BK)        // 24
#define SROW     20                 // padded row stride (floats) -> conflict-free
#define STAGEF   (128 * SROW)       // floats per matrix per stage
#define SMEM_TOT (NSTAGE * STAGEF * 2 * 4)   // 61440 bytes

__global__ __launch_bounds__(256, 2)
void gemm_mma_kernel(const float* __restrict__ A,
                     const float* __restrict__ W,
                     const float* __restrict__ bias,
                     float* __restrict__ C,
                     int Ntot) {
    extern __shared__ __align__(16) float sm[];
    float* Asm = sm;
    float* Bsm = sm + NSTAGE * STAGEF;

    const int tid  = threadIdx.x;
    const int warp = tid >> 5;
    const int lane = tid & 31;
    const int gid  = lane >> 2;     // 0..7
    const int tig  = lane & 3;      // 0..3
    const int wm   = warp & 1;      // warp row (2)
    const int wn   = warp >> 1;     // warp col (4)
    const int mb   = blockIdx.y * 128;
    const int nb   = blockIdx.x * 128;

    // Stage loader: 512 float4 per matrix per stage; thread handles f = tid, tid+256
    auto load_stage = [&](int s, int kt) {
        float* as = Asm + s * STAGEF;
        float* bs = Bsm + s * STAGEF;
        const int k0 = kt * BK;
        #pragma unroll
        for (int i = 0; i < 2; i++) {
            const int f  = tid + i * 256;
            const int m  = f >> 2;
            const int k4 = (f & 3) * 4;
            cpa16(smem_u32(as + m * SROW + k4), A + (size_t)(mb + m) * KTOT + k0 + k4);
            cpa16(smem_u32(bs + m * SROW + k4), W + (size_t)(nb + m) * KTOT + k0 + k4);
        }
    };

    float acc[4][4][4];
    #pragma unroll
    for (int mt = 0; mt < 4; mt++)
        #pragma unroll
        for (int nt = 0; nt < 4; nt++)
            #pragma unroll
            for (int r = 0; r < 4; r++) acc[mt][nt][r] = 0.0f;

    load_stage(0, 0); CP_COMMIT();
    load_stage(1, 1); CP_COMMIT();

    for (int kt = 0; kt < KITERS; ++kt) {
        CP_WAIT1();
        __syncthreads();

        const int s = kt % NSTAGE;
        if (kt + 2 < KITERS) load_stage((kt + 2) % NSTAGE, kt + 2);
        CP_COMMIT();   // empty group at tail keeps wait-count invariant

        const float* as = Asm + s * STAGEF;
        const float* bs = Bsm + s * STAGEF;

        #pragma unroll
        for (int ks = 0; ks < 2; ks++) {
            const int kb = ks * 8;
            uint32_t af[4][4], bf[4][2];
            #pragma unroll
            for (int mt = 0; mt < 4; mt++) {
                const int r0 = wm * 64 + mt * 16 + gid;
                af[mt][0] = __float_as_uint(as[(r0    ) * SROW + kb + tig    ]);
                af[mt][1] = __float_as_uint(as[(r0 + 8) * SROW + kb + tig    ]);
                af[mt][2] = __float_as_uint(as[(r0    ) * SROW + kb + tig + 4]);
                af[mt][3] = __float_as_uint(as[(r0 + 8) * SROW + kb + tig + 4]);
            }
            #pragma unroll
            for (int nt = 0; nt < 4; nt++) {
                const int c0 = wn * 32 + nt * 8 + gid;
                bf[nt][0] = __float_as_uint(bs[c0 * SROW + kb + tig    ]);
                bf[nt][1] = __float_as_uint(bs[c0 * SROW + kb + tig + 4]);
            }
            #pragma unroll
            for (int mt = 0; mt < 4; mt++)
                #pragma unroll
                for (int nt = 0; nt < 4; nt++)
                    mma_tf32(acc[mt][nt], af[mt], bf[nt]);
        }
    }

    // Epilogue: c0,c1 -> (row, col..col+1); c2,c3 -> (row+8, col..col+1)
    #pragma unroll
    for (int mt = 0; mt < 4; mt++) {
        const int row = mb + wm * 64 + mt * 16 + gid;
        #pragma unroll
        for (int nt = 0; nt < 4; nt++) {
            const int col = nb + wn * 32 + nt * 8 + 2 * tig;
            const float b0 = bias[col], b1 = bias[col + 1];
            float2 v0 = make_float2(acc[mt][nt][0] + b0, acc[mt][nt][1] + b1);
            float2 v1 = make_float2(acc[mt][nt][2] + b0, acc[mt][nt][3] + b1);
            *reinterpret_cast<float2*>(C + (size_t)row * Ntot + col)       = v0;
            *reinterpret_cast<float2*>(C + (size_t)(row + 8) * Ntot + col) = v1;
        }
    }
}

// ---------------------------------------------------------------------------
// Elementwise round-to-tf32 (RNA) pre-pass
// ---------------------------------------------------------------------------
__global__ void round_tf32_kernel(const float4* __restrict__ in,
                                  float4* __restrict__ out, int n4) {
    int i = blockIdx.x * blockDim.x + threadIdx.x;
    if (i < n4) {
        float4 v = in[i];
        v.x = tf32r(v.x); v.y = tf32r(v.y); v.z = tf32r(v.z); v.w = tf32r(v.w);
        out[i] = v;
    }
}

// ---------------------------------------------------------------------------
// Window attention (fp32): one CTA per (window, head); output tf32-rounded.
// ---------------------------------------------------------------------------
__global__ __launch_bounds__(256, 4)
void win_attn_kernel(const float* __restrict__ qkv,
                     const float* __restrict__ mask,
                     const float* __restrict__ rpb,
                     const int*   __restrict__ rel_idx,
                     float* __restrict__ attout) {
    const int w = blockIdx.x / NHEADS;
    const int h = blockIdx.x % NHEADS;
    const int tid = threadIdx.x;

    __shared__ float qs[NTOK][HD + 1];
    __shared__ float ks[NTOK][HD + 1];
    __shared__ float vs[NTOK][HD + 1];
    __shared__ float Ss[NTOK][NTOK + 1];

    const float* base = qkv + (size_t)w * NTOK * QKV_N + h * HD;
    for (int idx = tid; idx < NTOK * HD; idx += 256) {
        const int i = idx >> 5;
        const int d = idx & 31;
        const float* r = base + (size_t)i * QKV_N;
        qs[i][d] = r[d] * ATTN_SCALE;
        ks[i][d] = r[DIM + d];
        vs[i][d] = r[2 * DIM + d];
    }
    __syncthreads();

    const float* mrow = mask + (size_t)(w % NMASK) * NTOK * NTOK;
    for (int idx = tid; idx < NTOK * NTOK; idx += 256) {
        const int i = idx / NTOK;
        const int j = idx - i * NTOK;
        float s = 0.0f;
        #pragma unroll
        for (int d = 0; d < HD; d++)
            s = fmaf(qs[i][d], ks[j][d], s);
        s += rpb[rel_idx[idx] * NHEADS + h] + mrow[idx];
        Ss[i][j] = s;
    }
    __syncthreads();

    const int warp = tid >> 5;
    const int lane = tid & 31;
    for (int r = warp; r < NTOK; r += 8) {
        float v0 = Ss[r][lane];
        const bool has2 = (lane + 32) < NTOK;
        float v1 = has2 ? Ss[r][lane + 32] : -1e30f;
        float m = fmaxf(v0, v1);
        #pragma unroll
        for (int off = 16; off; off >>= 1)
            m = fmaxf(m, __shfl_xor_sync(0xffffffffu, m, off));
        float e0 = __expf(v0 - m);
        float e1 = has2 ? __expf(v1 - m) : 0.0f;
        float sum = e0 + e1;
        #pragma unroll
        for (int off = 16; off; off >>= 1)
            sum += __shfl_xor_sync(0xffffffffu, sum, off);
        const float inv = 1.0f / sum;
        Ss[r][lane] = e0 * inv;
        if (has2) Ss[r][lane + 32] = e1 * inv;
    }
    __syncthreads();

    float* obase = attout + (size_t)w * NTOK * DIM + h * HD;
    for (int idx = tid; idx < NTOK * HD; idx += 256) {
        const int i = idx >> 5;
        const int d = idx & 31;
        float o = 0.0f;
        #pragma unroll
        for (int j = 0; j < NTOK; j++)
            o = fmaf(Ss[i][j], vs[j][d], o);
        obase[(size_t)i * DIM + d] = tf32r(o);
    }
}

// ---------------------------------------------------------------------------
// Launch
// ---------------------------------------------------------------------------
extern "C" void kernel_launch(void* const* d_in, const int* in_sizes, int n_in,
                              void* d_out, int out_size) {
    const float* x      = (const float*)d_in[0];
    const float* mask   = (const float*)d_in[1];
    const float* rpb    = (const float*)d_in[2];
    const float* qkv_w  = (const float*)d_in[3];
    const float* qkv_b  = (const float*)d_in[4];
    const float* proj_w = (const float*)d_in[5];
    const float* proj_b = (const float*)d_in[6];
    const int*   rel_i  = (const int*)d_in[7];
    float* out = (float*)d_out;

    float *qkv_buf, *att_buf, *wq_buf, *wp_buf;
    cudaGetSymbolAddress((void**)&qkv_buf, g_qkv);
    cudaGetSymbolAddress((void**)&att_buf, g_att);
    cudaGetSymbolAddress((void**)&wq_buf, g_wq);
    cudaGetSymbolAddress((void**)&wp_buf, g_wp);

    cudaFuncSetAttribute(gemm_mma_kernel,
                         cudaFuncAttributeMaxDynamicSharedMemorySize, SMEM_TOT);

    // RN-round inputs to the tf32 grid (x -> g_att; weights -> scratch)
    {
        int n4 = (M_TOTAL * DIM) / 4;
        round_tf32_kernel<<<(n4 + 255) / 256, 256>>>((const float4*)x, (float4*)att_buf, n4);
        int w4 = (QKV_N * DIM) / 4;
        round_tf32_kernel<<<(w4 + 255) / 256, 256>>>((const float4*)qkv_w, (float4*)wq_buf, w4);
        int p4 = (DIM * DIM) / 4;
        round_tf32_kernel<<<(p4 + 255) / 256, 256>>>((const float4*)proj_w, (float4*)wp_buf, p4);
    }

    // 1) QKV projection (tf32 mma.sync)
    {
        dim3 grid(QKV_N / 128, M_TOTAL / 128);
        gemm_mma_kernel<<<grid, 256, SMEM_TOT>>>(att_buf, wq_buf, qkv_b, qkv_buf, QKV_N);
    }

    // 2) Windowed attention (fp32)
    win_attn_kernel<<<NWIN * NHEADS, 256>>>(qkv_buf, mask, rpb, rel_i, att_buf);

    // 3) Output projection (tf32 mma.sync)
    {
        dim3 grid(DIM / 128, M_TOTAL / 128);
        gemm_mma_kernel<<<grid, 256, SMEM_TOT>>>(att_buf, wp_buf, proj_b, out, DIM);
    }
}

// round 4
// speedup vs baseline: 2.6791x; 1.2070x over previous
#include <cuda_runtime.h>
#include <cstdint>
#include <math.h>

// ---------------------------------------------------------------------------
// Problem constants
// ---------------------------------------------------------------------------
#define NTOK      49
#define DIM       384
#define NHEADS    12
#define HD        32
#define NWIN      4096
#define NMASK     1024
#define M_TOTAL   (NWIN * NTOK)     // 200704
#define QKV_N     (3 * DIM)         // 1152
#define KTOT      384
#define ATTN_SCALE 0.17677669529663687f

// Scratch (__device__ globals; allocation-free rule)
__device__ __align__(128) float g_qkv[(size_t)M_TOTAL * QKV_N];
__device__ __align__(128) float g_att[(size_t)M_TOTAL * DIM];   // rounded-x, then attn out
__device__ __align__(128) float g_wq[QKV_N * DIM];
__device__ __align__(128) float g_wp[DIM * DIM];

// ---------------------------------------------------------------------------
// Helpers
// ---------------------------------------------------------------------------
__device__ __forceinline__ uint32_t smem_u32(const void* p) {
    uint32_t a;
    asm("{ .reg .u64 t; cvta.to.shared.u64 t, %1; cvt.u32.u64 %0, t; }" : "=r"(a) : "l"(p));
    return a;
}

__device__ __forceinline__ void cpa16(uint32_t dst, const void* src) {
    asm volatile("cp.async.cg.shared.global [%0], [%1], 16;" :: "r"(dst), "l"(src) : "memory");
}
#define CP_COMMIT() asm volatile("cp.async.commit_group;" ::: "memory")
#define CP_WAIT2()  asm volatile("cp.async.wait_group 2;" ::: "memory")

__device__ __forceinline__ float tf32r(float f) {
    float r;
    asm("cvt.rna.tf32.f32 %0, %1;" : "=f"(r) : "f"(f));
    return r;
}

__device__ __forceinline__ void mma_tf32(float* d, const uint32_t* a, const uint32_t* b) {
    asm volatile(
        "mma.sync.aligned.m16n8k8.row.col.f32.tf32.tf32.f32 "
        "{%0,%1,%2,%3}, {%4,%5,%6,%7}, {%8,%9}, {%0,%1,%2,%3};"
        : "+f"(d[0]), "+f"(d[1]), "+f"(d[2]), "+f"(d[3])
        : "r"(a[0]), "r"(a[1]), "r"(a[2]), "r"(a[3]), "r"(b[0]), "r"(b[1]));
}

// ---------------------------------------------------------------------------
// Tensor-core tf32 GEMM:  C[M,Ntot] = A[M,384] @ W[Ntot,384]^T + bias
// BM=BN=128, BK=16, 4-stage cp.async pipeline (2 in flight), 8 warps.
// ---------------------------------------------------------------------------
#define BK       16
#define NSTAGE   4
#define KITERS   (KTOT / BK)        // 24
#define SROW     20
#define STAGEF   (128 * SROW)
#define SMEM_TOT (NSTAGE * STAGEF * 2 * 4)   // 81920 bytes

__global__ __launch_bounds__(256, 2)
void gemm_mma_kernel(const float* __restrict__ A,
                     const float* __restrict__ W,
                     const float* __restrict__ bias,
                     float* __restrict__ C,
                     int Ntot) {
    extern __shared__ __align__(16) float sm[];
    float* Asm = sm;
    float* Bsm = sm + NSTAGE * STAGEF;

    const int tid  = threadIdx.x;
    const int warp = tid >> 5;
    const int lane = tid & 31;
    const int gid  = lane >> 2;
    const int tig  = lane & 3;
    const int wm   = warp & 1;
    const int wn   = warp >> 1;
    const int mb   = blockIdx.y * 128;
    const int nb   = blockIdx.x * 128;

    auto load_stage = [&](int s, int kt) {
        float* as = Asm + s * STAGEF;
        float* bs = Bsm + s * STAGEF;
        const int k0 = kt * BK;
        #pragma unroll
        for (int i = 0; i < 2; i++) {
            const int f  = tid + i * 256;
            const int m  = f >> 2;
            const int k4 = (f & 3) * 4;
            cpa16(smem_u32(as + m * SROW + k4), A + (size_t)(mb + m) * KTOT + k0 + k4);
            cpa16(smem_u32(bs + m * SROW + k4), W + (size_t)(nb + m) * KTOT + k0 + k4);
        }
    };

    float acc[4][4][4];
    #pragma unroll
    for (int mt = 0; mt < 4; mt++)
        #pragma unroll
        for (int nt = 0; nt < 4; nt++)
            #pragma unroll
            for (int r = 0; r < 4; r++) acc[mt][nt][r] = 0.0f;

    load_stage(0, 0); CP_COMMIT();
    load_stage(1, 1); CP_COMMIT();
    load_stage(2, 2); CP_COMMIT();

    for (int kt = 0; kt < KITERS; ++kt) {
        CP_WAIT2();
        __syncthreads();

        const int s = kt % NSTAGE;
        if (kt + 3 < KITERS) load_stage((kt + 3) % NSTAGE, kt + 3);
        CP_COMMIT();

        const float* as = Asm + s * STAGEF;
        const float* bs = Bsm + s * STAGEF;

        #pragma unroll
        for (int ks = 0; ks < 2; ks++) {
            const int kb = ks * 8;
            uint32_t af[4][4], bf[4][2];
            #pragma unroll
            for (int mt = 0; mt < 4; mt++) {
                const int r0 = wm * 64 + mt * 16 + gid;
                af[mt][0] = __float_as_uint(as[(r0    ) * SROW + kb + tig    ]);
                af[mt][1] = __float_as_uint(as[(r0 + 8) * SROW + kb + tig    ]);
                af[mt][2] = __float_as_uint(as[(r0    ) * SROW + kb + tig + 4]);
                af[mt][3] = __float_as_uint(as[(r0 + 8) * SROW + kb + tig + 4]);
            }
            #pragma unroll
            for (int nt = 0; nt < 4; nt++) {
                const int c0 = wn * 32 + nt * 8 + gid;
                bf[nt][0] = __float_as_uint(bs[c0 * SROW + kb + tig    ]);
                bf[nt][1] = __float_as_uint(bs[c0 * SROW + kb + tig + 4]);
            }
            #pragma unroll
            for (int mt = 0; mt < 4; mt++)
                #pragma unroll
                for (int nt = 0; nt < 4; nt++)
                    mma_tf32(acc[mt][nt], af[mt], bf[nt]);
        }
    }

    #pragma unroll
    for (int mt = 0; mt < 4; mt++) {
        const int row = mb + wm * 64 + mt * 16 + gid;
        #pragma unroll
        for (int nt = 0; nt < 4; nt++) {
            const int col = nb + wn * 32 + nt * 8 + 2 * tig;
            const float b0 = bias[col], b1 = bias[col + 1];
            float2 v0 = make_float2(acc[mt][nt][0] + b0, acc[mt][nt][1] + b1);
            float2 v1 = make_float2(acc[mt][nt][2] + b0, acc[mt][nt][3] + b1);
            *reinterpret_cast<float2*>(C + (size_t)row * Ntot + col)       = v0;
            *reinterpret_cast<float2*>(C + (size_t)(row + 8) * Ntot + col) = v1;
        }
    }
}

// ---------------------------------------------------------------------------
// Elementwise round-to-tf32 (RNA) pre-pass
// ---------------------------------------------------------------------------
__global__ void round_tf32_kernel(const float4* __restrict__ in,
                                  float4* __restrict__ out, int n4) {
    int i = blockIdx.x * blockDim.x + threadIdx.x;
    if (i < n4) {
        float4 v = in[i];
        v.x = tf32r(v.x); v.y = tf32r(v.y); v.z = tf32r(v.z); v.w = tf32r(v.w);
        out[i] = v;
    }
}

// ---------------------------------------------------------------------------
// Window attention v2: one CTA per (window, head), register-tiled phases.
//   qt/kt transposed [d][i] (pad 52), scores stored transposed St[j][i].
// ---------------------------------------------------------------------------
#define SP 52   // padded token stride (13 float4)
#define VP 36   // padded V row stride (9 float4)

__global__ __launch_bounds__(192, 5)
void win_attn_kernel(const float* __restrict__ qkv,
                     const float* __restrict__ mask,
                     const float* __restrict__ rpb,
                     const int*   __restrict__ rel_idx,
                     float* __restrict__ attout) {
    const int w = blockIdx.x / NHEADS;
    const int h = blockIdx.x % NHEADS;
    const int tid = threadIdx.x;

    __shared__ float qt[HD][SP];          // qt[d][i], pre-scaled
    __shared__ float kt[HD][SP];          // kt[d][j]
    __shared__ float vs[NTOK][VP];        // v row-major
    __shared__ float St[SP][SP];          // scores transposed: St[j][i]; becomes P

    // ---- Load: 3 * 49 rows * 8 float4-granules = 1176 granules ----
    const float* base = qkv + (size_t)w * NTOK * QKV_N + h * HD;
    for (int idx = tid; idx < 3 * NTOK * 8; idx += 192) {
        const int m  = idx / (NTOK * 8);
        const int g  = idx - m * (NTOK * 8);
        const int i  = g >> 3;
        const int d4 = (g & 7) * 4;
        float4 v = *reinterpret_cast<const float4*>(base + (size_t)i * QKV_N + m * DIM + d4);
        if (m == 0) {
            qt[d4 + 0][i] = v.x * ATTN_SCALE;
            qt[d4 + 1][i] = v.y * ATTN_SCALE;
            qt[d4 + 2][i] = v.z * ATTN_SCALE;
            qt[d4 + 3][i] = v.w * ATTN_SCALE;
        } else if (m == 1) {
            kt[d4 + 0][i] = v.x;
            kt[d4 + 1][i] = v.y;
            kt[d4 + 2][i] = v.z;
            kt[d4 + 3][i] = v.w;
        } else {
            *reinterpret_cast<float4*>(&vs[i][d4]) = v;
        }
    }
    __syncthreads();

    // ---- Scores: 4x4 tile per thread, 169 threads ----
    if (tid < 169) {
        const int ti = tid % 13;
        const int tj = tid / 13;
        const int i0 = ti * 4;
        const int j0 = tj * 4;
        float acc[4][4];   // [jj][ii]
        #pragma unroll
        for (int a = 0; a < 4; a++)
            #pragma unroll
            for (int b = 0; b < 4; b++) acc[a][b] = 0.0f;

        #pragma unroll
        for (int d = 0; d < HD; d++) {
            float4 qv = *reinterpret_cast<const float4*>(&qt[d][i0]);
            float4 kv = *reinterpret_cast<const float4*>(&kt[d][j0]);
            const float qa[4] = {qv.x, qv.y, qv.z, qv.w};
            const float ka[4] = {kv.x, kv.y, kv.z, kv.w};
            #pragma unroll
            for (int jj = 0; jj < 4; jj++)
                #pragma unroll
                for (int ii = 0; ii < 4; ii++)
                    acc[jj][ii] = fmaf(ka[jj], qa[ii], acc[jj][ii]);
        }

        const float* mrow = mask + (size_t)(w % NMASK) * NTOK * NTOK;
        #pragma unroll
        for (int jj = 0; jj < 4; jj++) {
            const int j = j0 + jj;
            #pragma unroll
            for (int ii = 0; ii < 4; ii++) {
                const int i = i0 + ii;
                if (i < NTOK && j < NTOK) {
                    const int e = i * NTOK + j;
                    St[j][i] = acc[jj][ii] + rpb[rel_idx[e] * NHEADS + h] + mrow[e];
                }
            }
        }
    }
    __syncthreads();

    // ---- Softmax down columns of St (thread i) ----
    if (tid < NTOK) {
        const int i = tid;
        float m0 = -1e30f, m1 = -1e30f, m2 = -1e30f, m3 = -1e30f;
        #pragma unroll
        for (int j = 0; j < 48; j += 4) {
            m0 = fmaxf(m0, St[j + 0][i]);
            m1 = fmaxf(m1, St[j + 1][i]);
            m2 = fmaxf(m2, St[j + 2][i]);
            m3 = fmaxf(m3, St[j + 3][i]);
        }
        float m = fmaxf(fmaxf(m0, m1), fmaxf(fmaxf(m2, m3), St[48][i]));
        float s0 = 0.f, s1 = 0.f, s2 = 0.f, s3 = 0.f;
        #pragma unroll
        for (int j = 0; j < 48; j += 4) {
            float e0 = __expf(St[j + 0][i] - m);
            float e1 = __expf(St[j + 1][i] - m);
            float e2 = __expf(St[j + 2][i] - m);
            float e3 = __expf(St[j + 3][i] - m);
            St[j + 0][i] = e0; St[j + 1][i] = e1;
            St[j + 2][i] = e2; St[j + 3][i] = e3;
            s0 += e0; s1 += e1; s2 += e2; s3 += e3;
        }
        float el = __expf(St[48][i] - m);
        St[48][i] = el;
        const float inv = 1.0f / (s0 + s1 + s2 + s3 + el);
        #pragma unroll
        for (int j = 0; j < NTOK; j++) St[j][i] *= inv;
    }
    __syncthreads();

    // ---- PV: 4x4 tile per thread (i x d), 104 threads ----
    if (tid < 104) {
        const int ti = tid % 13;
        const int td = tid / 13;
        const int i0 = ti * 4;
        const int d0 = td * 4;
        float acc[4][4];   // [ii][dd]
        #pragma unroll
        for (int a = 0; a < 4; a++)
            #pragma unroll
            for (int b = 0; b < 4; b++) acc[a][b] = 0.0f;

        for (int j = 0; j < NTOK; j++) {
            float4 pv = *reinterpret_cast<const float4*>(&St[j][i0]);
            float4 vv = *reinterpret_cast<const float4*>(&vs[j][d0]);
            const float pa[4] = {pv.x, pv.y, pv.z, pv.w};
            const float va[4] = {vv.x, vv.y, vv.z, vv.w};
            #pragma unroll
            for (int ii = 0; ii < 4; ii++)
                #pragma unroll
                for (int dd = 0; dd < 4; dd++)
                    acc[ii][dd] = fmaf(pa[ii], va[dd], acc[ii][dd]);
        }

        float* obase = attout + (size_t)w * NTOK * DIM + h * HD;
        #pragma unroll
        for (int ii = 0; ii < 4; ii++) {
            const int i = i0 + ii;
            if (i < NTOK) {
                float4 o;
                o.x = tf32r(acc[ii][0]); o.y = tf32r(acc[ii][1]);
                o.z = tf32r(acc[ii][2]); o.w = tf32r(acc[ii][3]);
                *reinterpret_cast<float4*>(obase + (size_t)i * DIM + d0) = o;
            }
        }
    }
}

// ---------------------------------------------------------------------------
// Launch
// ---------------------------------------------------------------------------
extern "C" void kernel_launch(void* const* d_in, const int* in_sizes, int n_in,
                              void* d_out, int out_size) {
    const float* x      = (const float*)d_in[0];
    const float* mask   = (const float*)d_in[1];
    const float* rpb    = (const float*)d_in[2];
    const float* qkv_w  = (const float*)d_in[3];
    const float* qkv_b  = (const float*)d_in[4];
    const float* proj_w = (const float*)d_in[5];
    const float* proj_b = (const float*)d_in[6];
    const int*   rel_i  = (const int*)d_in[7];
    float* out = (float*)d_out;

    float *qkv_buf, *att_buf, *wq_buf, *wp_buf;
    cudaGetSymbolAddress((void**)&qkv_buf, g_qkv);
    cudaGetSymbolAddress((void**)&att_buf, g_att);
    cudaGetSymbolAddress((void**)&wq_buf, g_wq);
    cudaGetSymbolAddress((void**)&wp_buf, g_wp);

    cudaFuncSetAttribute(gemm_mma_kernel,
                         cudaFuncAttributeMaxDynamicSharedMemorySize, SMEM_TOT);

    {
        int n4 = (M_TOTAL * DIM) / 4;
        round_tf32_kernel<<<(n4 + 255) / 256, 256>>>((const float4*)x, (float4*)att_buf, n4);
        int w4 = (QKV_N * DIM) / 4;
        round_tf32_kernel<<<(w4 + 255) / 256, 256>>>((const float4*)qkv_w, (float4*)wq_buf, w4);
        int p4 = (DIM * DIM) / 4;
        round_tf32_kernel<<<(p4 + 255) / 256, 256>>>((const float4*)proj_w, (float4*)wp_buf, p4);
    }

    {
        dim3 grid(QKV_N / 128, M_TOTAL / 128);
        gemm_mma_kernel<<<grid, 256, SMEM_TOT>>>(att_buf, wq_buf, qkv_b, qkv_buf, QKV_N);
    }

    win_attn_kernel<<<NWIN * NHEADS, 192>>>(qkv_buf, mask, rpb, rel_i, att_buf);

    {
        dim3 grid(DIM / 128, M_TOTAL / 128);
        gemm_mma_kernel<<<grid, 256, SMEM_TOT>>>(att_buf, wp_buf, proj_b, out, DIM);
    }
}

// round 5
// speedup vs baseline: 3.7242x; 1.3901x over previous
#include <cuda_runtime.h>
#include <cuda_fp16.h>
#include <cstdint>
#include <math.h>

// ---------------------------------------------------------------------------
// Problem constants
// ---------------------------------------------------------------------------
#define NTOK      49
#define DIM       384
#define NHEADS    12
#define HD        32
#define NWIN      4096
#define NMASK     1024
#define M_TOTAL   (NWIN * NTOK)     // 200704
#define QKV_N     (3 * DIM)         // 1152
#define KTOT      384
#define ATTN_SCALE 0.17677669529663687f

// Scratch (__device__ globals; allocation-free rule)
__device__ __align__(128) float  g_qkv[(size_t)M_TOTAL * QKV_N];   // fp32 qkv
__device__ __align__(128) __half g_xh [(size_t)M_TOTAL * DIM];     // fp16 x
__device__ __align__(128) __half g_ah [(size_t)M_TOTAL * DIM];     // fp16 attn out
__device__ __align__(128) __half g_wqh[QKV_N * DIM];
__device__ __align__(128) __half g_wph[DIM * DIM];

// ---------------------------------------------------------------------------
// Helpers
// ---------------------------------------------------------------------------
__device__ __forceinline__ uint32_t smem_u32(const void* p) {
    uint32_t a;
    asm("{ .reg .u64 t; cvta.to.shared.u64 t, %1; cvt.u32.u64 %0, t; }" : "=r"(a) : "l"(p));
    return a;
}

__device__ __forceinline__ void cpa16(uint32_t dst, const void* src) {
    asm volatile("cp.async.cg.shared.global [%0], [%1], 16;" :: "r"(dst), "l"(src) : "memory");
}
#define CP_COMMIT() asm volatile("cp.async.commit_group;" ::: "memory")
#define CP_WAIT1()  asm volatile("cp.async.wait_group 1;" ::: "memory")

__device__ __forceinline__ void mma_f16(float* d, const uint32_t* a, const uint32_t* b) {
    asm volatile(
        "mma.sync.aligned.m16n8k16.row.col.f32.f16.f16.f32 "
        "{%0,%1,%2,%3}, {%4,%5,%6,%7}, {%8,%9}, {%0,%1,%2,%3};"
        : "+f"(d[0]), "+f"(d[1]), "+f"(d[2]), "+f"(d[3])
        : "r"(a[0]), "r"(a[1]), "r"(a[2]), "r"(a[3]), "r"(b[0]), "r"(b[1]));
}

// ---------------------------------------------------------------------------
// fp16 tensor-core GEMM:  C[M,Ntot](fp32) = A[M,384](fp16) @ W[Ntot,384]^T + bias
// BM=BN=128, BK=32 halves, 3-stage cp.async, 8 warps x (64x32) tiles.
// ---------------------------------------------------------------------------
#define BKH      32                  // halves per k-chunk
#define NSTAGE   3
#define KITERS   (KTOT / BKH)        // 12
#define SROWW    20                  // padded row stride in 32-bit words (40 halves)
#define STAGEW   (128 * SROWW)       // words per matrix per stage
#define SMEM_TOT (NSTAGE * STAGEW * 2 * 4)   // 61440 bytes

__global__ __launch_bounds__(256, 2)
void gemm_mma_kernel(const __half* __restrict__ A,
                     const __half* __restrict__ W,
                     const float* __restrict__ bias,
                     float* __restrict__ C,
                     int Ntot) {
    extern __shared__ __align__(16) uint32_t sm[];
    uint32_t* Asm = sm;
    uint32_t* Bsm = sm + NSTAGE * STAGEW;

    const int tid  = threadIdx.x;
    const int warp = tid >> 5;
    const int lane = tid & 31;
    const int gid  = lane >> 2;
    const int tig  = lane & 3;
    const int wm   = warp & 1;
    const int wn   = warp >> 1;
    const int mb   = blockIdx.y * 128;
    const int nb   = blockIdx.x * 128;

    // per stage per matrix: 128 rows x 4 granules(16B=8 halves) = 512 granules
    auto load_stage = [&](int s, int kt) {
        uint32_t* as = Asm + s * STAGEW;
        uint32_t* bs = Bsm + s * STAGEW;
        const int k0 = kt * BKH;
        #pragma unroll
        for (int i = 0; i < 2; i++) {
            const int f = tid + i * 256;
            const int m = f >> 2;
            const int g = f & 3;
            cpa16(smem_u32(as + m * SROWW + g * 4), A + (size_t)(mb + m) * KTOT + k0 + g * 8);
            cpa16(smem_u32(bs + m * SROWW + g * 4), W + (size_t)(nb + m) * KTOT + k0 + g * 8);
        }
    };

    float acc[4][4][4];
    #pragma unroll
    for (int mt = 0; mt < 4; mt++)
        #pragma unroll
        for (int nt = 0; nt < 4; nt++)
            #pragma unroll
            for (int r = 0; r < 4; r++) acc[mt][nt][r] = 0.0f;

    load_stage(0, 0); CP_COMMIT();
    load_stage(1, 1); CP_COMMIT();

    for (int kt = 0; kt < KITERS; ++kt) {
        CP_WAIT1();
        __syncthreads();

        const int s = kt % NSTAGE;
        if (kt + 2 < KITERS) load_stage((kt + 2) % NSTAGE, kt + 2);
        CP_COMMIT();

        const uint32_t* as = Asm + s * STAGEW;
        const uint32_t* bs = Bsm + s * STAGEW;

        #pragma unroll
        for (int ks = 0; ks < 2; ks++) {        // two k16 steps per 32-half chunk
            const int kw = ks * 8;              // word offset of this k16 block
            uint32_t af[4][4], bf[4][2];
            #pragma unroll
            for (int mt = 0; mt < 4; mt++) {
                const int r0 = wm * 64 + mt * 16 + gid;
                af[mt][0] = as[(r0    ) * SROWW + kw + tig    ];
                af[mt][1] = as[(r0 + 8) * SROWW + kw + tig    ];
                af[mt][2] = as[(r0    ) * SROWW + kw + tig + 4];
                af[mt][3] = as[(r0 + 8) * SROWW + kw + tig + 4];
            }
            #pragma unroll
            for (int nt = 0; nt < 4; nt++) {
                const int c0 = wn * 32 + nt * 8 + gid;
                bf[nt][0] = bs[c0 * SROWW + kw + tig    ];
                bf[nt][1] = bs[c0 * SROWW + kw + tig + 4];
            }
            #pragma unroll
            for (int mt = 0; mt < 4; mt++)
                #pragma unroll
                for (int nt = 0; nt < 4; nt++)
                    mma_f16(acc[mt][nt], af[mt], bf[nt]);
        }
    }

    #pragma unroll
    for (int mt = 0; mt < 4; mt++) {
        const int row = mb + wm * 64 + mt * 16 + gid;
        #pragma unroll
        for (int nt = 0; nt < 4; nt++) {
            const int col = nb + wn * 32 + nt * 8 + 2 * tig;
            const float b0 = bias[col], b1 = bias[col + 1];
            float2 v0 = make_float2(acc[mt][nt][0] + b0, acc[mt][nt][1] + b1);
            float2 v1 = make_float2(acc[mt][nt][2] + b0, acc[mt][nt][3] + b1);
            *reinterpret_cast<float2*>(C + (size_t)row * Ntot + col)       = v0;
            *reinterpret_cast<float2*>(C + (size_t)(row + 8) * Ntot + col) = v1;
        }
    }
}

// ---------------------------------------------------------------------------
// fp32 -> fp16 conversion pass
// ---------------------------------------------------------------------------
__global__ void f2h_kernel(const float4* __restrict__ in,
                           uint2* __restrict__ out, int n4) {
    int i = blockIdx.x * blockDim.x + threadIdx.x;
    if (i < n4) {
        float4 v = in[i];
        __half2 h0 = __floats2half2_rn(v.x, v.y);
        __half2 h1 = __floats2half2_rn(v.z, v.w);
        uint2 u;
        u.x = *reinterpret_cast<uint32_t*>(&h0);
        u.y = *reinterpret_cast<uint32_t*>(&h1);
        out[i] = u;
    }
}

// ---------------------------------------------------------------------------
// Window attention: one CTA per (window, head), register-tiled, fp32 math,
// fp16 output (feeds GEMM2).
// ---------------------------------------------------------------------------
#define SP 52   // padded token stride (13 float4)
#define VP 36   // padded V row stride (9 float4)

__global__ __launch_bounds__(192, 5)
void win_attn_kernel(const float* __restrict__ qkv,
                     const float* __restrict__ mask,
                     const float* __restrict__ rpb,
                     const int*   __restrict__ rel_idx,
                     __half* __restrict__ attout) {
    const int w = blockIdx.x / NHEADS;
    const int h = blockIdx.x % NHEADS;
    const int tid = threadIdx.x;

    __shared__ float qt[HD][SP];
    __shared__ float kt[HD][SP];
    __shared__ float vs[NTOK][VP];
    __shared__ float St[SP][SP];

    const float* base = qkv + (size_t)w * NTOK * QKV_N + h * HD;
    for (int idx = tid; idx < 3 * NTOK * 8; idx += 192) {
        const int m  = idx / (NTOK * 8);
        const int g  = idx - m * (NTOK * 8);
        const int i  = g >> 3;
        const int d4 = (g & 7) * 4;
        float4 v = *reinterpret_cast<const float4*>(base + (size_t)i * QKV_N + m * DIM + d4);
        if (m == 0) {
            qt[d4 + 0][i] = v.x * ATTN_SCALE;
            qt[d4 + 1][i] = v.y * ATTN_SCALE;
            qt[d4 + 2][i] = v.z * ATTN_SCALE;
            qt[d4 + 3][i] = v.w * ATTN_SCALE;
        } else if (m == 1) {
            kt[d4 + 0][i] = v.x;
            kt[d4 + 1][i] = v.y;
            kt[d4 + 2][i] = v.z;
            kt[d4 + 3][i] = v.w;
        } else {
            *reinterpret_cast<float4*>(&vs[i][d4]) = v;
        }
    }
    __syncthreads();

    if (tid < 169) {
        const int ti = tid % 13;
        const int tj = tid / 13;
        const int i0 = ti * 4;
        const int j0 = tj * 4;
        float acc[4][4];
        #pragma unroll
        for (int a = 0; a < 4; a++)
            #pragma unroll
            for (int b = 0; b < 4; b++) acc[a][b] = 0.0f;

        #pragma unroll
        for (int d = 0; d < HD; d++) {
            float4 qv = *reinterpret_cast<const float4*>(&qt[d][i0]);
            float4 kv = *reinterpret_cast<const float4*>(&kt[d][j0]);
            const float qa[4] = {qv.x, qv.y, qv.z, qv.w};
            const float ka[4] = {kv.x, kv.y, kv.z, kv.w};
            #pragma unroll
            for (int jj = 0; jj < 4; jj++)
                #pragma unroll
                for (int ii = 0; ii < 4; ii++)
                    acc[jj][ii] = fmaf(ka[jj], qa[ii], acc[jj][ii]);
        }

        const float* mrow = mask + (size_t)(w % NMASK) * NTOK * NTOK;
        #pragma unroll
        for (int jj = 0; jj < 4; jj++) {
            const int j = j0 + jj;
            #pragma unroll
            for (int ii = 0; ii < 4; ii++) {
                const int i = i0 + ii;
                if (i < NTOK && j < NTOK) {
                    const int e = i * NTOK + j;
                    St[j][i] = acc[jj][ii] + rpb[rel_idx[e] * NHEADS + h] + mrow[e];
                }
            }
        }
    }
    __syncthreads();

    if (tid < NTOK) {
        const int i = tid;
        float m0 = -1e30f, m1 = -1e30f, m2 = -1e30f, m3 = -1e30f;
        #pragma unroll
        for (int j = 0; j < 48; j += 4) {
            m0 = fmaxf(m0, St[j + 0][i]);
            m1 = fmaxf(m1, St[j + 1][i]);
            m2 = fmaxf(m2, St[j + 2][i]);
            m3 = fmaxf(m3, St[j + 3][i]);
        }
        float m = fmaxf(fmaxf(m0, m1), fmaxf(fmaxf(m2, m3), St[48][i]));
        float s0 = 0.f, s1 = 0.f, s2 = 0.f, s3 = 0.f;
        #pragma unroll
        for (int j = 0; j < 48; j += 4) {
            float e0 = __expf(St[j + 0][i] - m);
            float e1 = __expf(St[j + 1][i] - m);
            float e2 = __expf(St[j + 2][i] - m);
            float e3 = __expf(St[j + 3][i] - m);
            St[j + 0][i] = e0; St[j + 1][i] = e1;
            St[j + 2][i] = e2; St[j + 3][i] = e3;
            s0 += e0; s1 += e1; s2 += e2; s3 += e3;
        }
        float el = __expf(St[48][i] - m);
        St[48][i] = el;
        const float inv = 1.0f / (s0 + s1 + s2 + s3 + el);
        #pragma unroll
        for (int j = 0; j < NTOK; j++) St[j][i] *= inv;
    }
    __syncthreads();

    if (tid < 104) {
        const int ti = tid % 13;
        const int td = tid / 13;
        const int i0 = ti * 4;
        const int d0 = td * 4;
        float acc[4][4];
        #pragma unroll
        for (int a = 0; a < 4; a++)
            #pragma unroll
            for (int b = 0; b < 4; b++) acc[a][b] = 0.0f;

        for (int j = 0; j < NTOK; j++) {
            float4 pv = *reinterpret_cast<const float4*>(&St[j][i0]);
            float4 vv = *reinterpret_cast<const float4*>(&vs[j][d0]);
            const float pa[4] = {pv.x, pv.y, pv.z, pv.w};
            const float va[4] = {vv.x, vv.y, vv.z, vv.w};
            #pragma unroll
            for (int ii = 0; ii < 4; ii++)
                #pragma unroll
                for (int dd = 0; dd < 4; dd++)
                    acc[ii][dd] = fmaf(pa[ii], va[dd], acc[ii][dd]);
        }

        __half* obase = attout + (size_t)w * NTOK * DIM + h * HD;
        #pragma unroll
        for (int ii = 0; ii < 4; ii++) {
            const int i = i0 + ii;
            if (i < NTOK) {
                __half2 p0 = __floats2half2_rn(acc[ii][0], acc[ii][1]);
                __half2 p1 = __floats2half2_rn(acc[ii][2], acc[ii][3]);
                uint2 u;
                u.x = *reinterpret_cast<uint32_t*>(&p0);
                u.y = *reinterpret_cast<uint32_t*>(&p1);
                *reinterpret_cast<uint2*>(obase + (size_t)i * DIM + d0) = u;
            }
        }
    }
}

// ---------------------------------------------------------------------------
// Launch
// ---------------------------------------------------------------------------
extern "C" void kernel_launch(void* const* d_in, const int* in_sizes, int n_in,
                              void* d_out, int out_size) {
    const float* x      = (const float*)d_in[0];
    const float* mask   = (const float*)d_in[1];
    const float* rpb    = (const float*)d_in[2];
    const float* qkv_w  = (const float*)d_in[3];
    const float* qkv_b  = (const float*)d_in[4];
    const float* proj_w = (const float*)d_in[5];
    const float* proj_b = (const float*)d_in[6];
    const int*   rel_i  = (const int*)d_in[7];
    float* out = (float*)d_out;

    float *qkv_buf;
    __half *xh, *ah, *wqh, *wph;
    cudaGetSymbolAddress((void**)&qkv_buf, g_qkv);
    cudaGetSymbolAddress((void**)&xh,  g_xh);
    cudaGetSymbolAddress((void**)&ah,  g_ah);
    cudaGetSymbolAddress((void**)&wqh, g_wqh);
    cudaGetSymbolAddress((void**)&wph, g_wph);

    cudaFuncSetAttribute(gemm_mma_kernel,
                         cudaFuncAttributeMaxDynamicSharedMemorySize, SMEM_TOT);

    // fp32 -> fp16 conversions
    {
        int n4 = (M_TOTAL * DIM) / 4;
        f2h_kernel<<<(n4 + 255) / 256, 256>>>((const float4*)x, (uint2*)xh, n4);
        int w4 = (QKV_N * DIM) / 4;
        f2h_kernel<<<(w4 + 255) / 256, 256>>>((const float4*)qkv_w, (uint2*)wqh, w4);
        int p4 = (DIM * DIM) / 4;
        f2h_kernel<<<(p4 + 255) / 256, 256>>>((const float4*)proj_w, (uint2*)wph, p4);
    }

    // 1) QKV projection (fp16 mma, fp32 accum/out)
    {
        dim3 grid(QKV_N / 128, M_TOTAL / 128);
        gemm_mma_kernel<<<grid, 256, SMEM_TOT>>>(xh, wqh, qkv_b, qkv_buf, QKV_N);
    }

    // 2) Windowed attention (fp32 math, fp16 out)
    win_attn_kernel<<<NWIN * NHEADS, 192>>>(qkv_buf, mask, rpb, rel_i, ah);

    // 3) Output projection (fp16 mma, fp32 out)
    {
        dim3 grid(DIM / 128, M_TOTAL / 128);
        gemm_mma_kernel<<<grid, 256, SMEM_TOT>>>(ah, wph, proj_b, out, DIM);
    }
}

// round 6
// speedup vs baseline: 4.5823x; 1.2304x over previous
#include <cuda_runtime.h>
#include <cuda_fp16.h>
#include <cstdint>
#include <math.h>

// ---------------------------------------------------------------------------
// Problem constants
// ---------------------------------------------------------------------------
#define NTOK      49
#define DIM       384
#define NHEADS    12
#define HD        32
#define NWIN      4096
#define NMASK     1024
#define M_TOTAL   (NWIN * NTOK)     // 200704
#define QKV_N     (3 * DIM)         // 1152
#define KTOT      384
#define ATTN_SCALE 0.17677669529663687f

// Scratch (__device__ globals; allocation-free rule)
__device__ __align__(128) __half g_qkvh[(size_t)M_TOTAL * QKV_N];  // fp16 qkv
__device__ __align__(128) __half g_xh [(size_t)M_TOTAL * DIM];     // fp16 x
__device__ __align__(128) __half g_ah [(size_t)M_TOTAL * DIM];     // fp16 attn out
__device__ __align__(128) __half g_wqh[QKV_N * DIM];
__device__ __align__(128) __half g_wph[DIM * DIM];

// ---------------------------------------------------------------------------
// Helpers
// ---------------------------------------------------------------------------
__device__ __forceinline__ uint32_t smem_u32(const void* p) {
    uint32_t a;
    asm("{ .reg .u64 t; cvta.to.shared.u64 t, %1; cvt.u32.u64 %0, t; }" : "=r"(a) : "l"(p));
    return a;
}

__device__ __forceinline__ void cpa16(uint32_t dst, const void* src) {
    asm volatile("cp.async.cg.shared.global [%0], [%1], 16;" :: "r"(dst), "l"(src) : "memory");
}
#define CP_COMMIT() asm volatile("cp.async.commit_group;" ::: "memory")
#define CP_WAIT1()  asm volatile("cp.async.wait_group 1;" ::: "memory")

__device__ __forceinline__ void mma_f16(float* d, const uint32_t* a, const uint32_t* b) {
    asm volatile(
        "mma.sync.aligned.m16n8k16.row.col.f32.f16.f16.f32 "
        "{%0,%1,%2,%3}, {%4,%5,%6,%7}, {%8,%9}, {%0,%1,%2,%3};"
        : "+f"(d[0]), "+f"(d[1]), "+f"(d[2]), "+f"(d[3])
        : "r"(a[0]), "r"(a[1]), "r"(a[2]), "r"(a[3]), "r"(b[0]), "r"(b[1]));
}

__device__ __forceinline__ void ldsm_x4(uint32_t* r, uint32_t addr) {
    asm volatile("ldmatrix.sync.aligned.m8n8.x4.shared.b16 {%0,%1,%2,%3}, [%4];"
                 : "=r"(r[0]), "=r"(r[1]), "=r"(r[2]), "=r"(r[3]) : "r"(addr));
}

// ---------------------------------------------------------------------------
// fp16 tensor-core GEMM:  C[M,Ntot] = A[M,384](fp16) @ W[Ntot,384]^T + bias
// BM=BN=128, BK=32 halves, 3-stage cp.async, 8 warps x (64x32), ldmatrix frags.
// ---------------------------------------------------------------------------
#define BKH      32
#define NSTAGE   3
#define KITERS   (KTOT / BKH)        // 12
#define SROWW    20                  // row stride in words (40 halves)
#define STAGEW   (128 * SROWW)
#define SMEM_TOT (NSTAGE * STAGEW * 2 * 4)   // 61440 bytes

template <typename OutT>
__global__ __launch_bounds__(256, 2)
void gemm_mma_kernel(const __half* __restrict__ A,
                     const __half* __restrict__ W,
                     const float* __restrict__ bias,
                     OutT* __restrict__ C,
                     int Ntot) {
    extern __shared__ __align__(16) uint32_t sm[];
    uint32_t* Asm = sm;
    uint32_t* Bsm = sm + NSTAGE * STAGEW;

    const int tid  = threadIdx.x;
    const int warp = tid >> 5;
    const int lane = tid & 31;
    const int gid  = lane >> 2;
    const int tig  = lane & 3;
    const int wm   = warp & 1;
    const int wn   = warp >> 1;
    const int mb   = blockIdx.y * 128;
    const int nb   = blockIdx.x * 128;

    // ldmatrix lane offsets (in words)
    const int aLane = ((lane & 7) + 8 * ((lane >> 3) & 1)) * SROWW + 4 * (lane >> 4);
    const int bLane = ((lane & 7) + 8 * (lane >> 4)) * SROWW + 4 * ((lane >> 3) & 1);

    auto load_stage = [&](int s, int kt) {
        uint32_t* as = Asm + s * STAGEW;
        uint32_t* bs = Bsm + s * STAGEW;
        const int k0 = kt * BKH;
        #pragma unroll
        for (int i = 0; i < 2; i++) {
            const int f = tid + i * 256;
            const int m = f >> 2;
            const int g = f & 3;
            cpa16(smem_u32(as + m * SROWW + g * 4), A + (size_t)(mb + m) * KTOT + k0 + g * 8);
            cpa16(smem_u32(bs + m * SROWW + g * 4), W + (size_t)(nb + m) * KTOT + k0 + g * 8);
        }
    };

    float acc[4][4][4];
    #pragma unroll
    for (int mt = 0; mt < 4; mt++)
        #pragma unroll
        for (int nt = 0; nt < 4; nt++)
            #pragma unroll
            for (int r = 0; r < 4; r++) acc[mt][nt][r] = 0.0f;

    load_stage(0, 0); CP_COMMIT();
    load_stage(1, 1); CP_COMMIT();

    for (int kt = 0; kt < KITERS; ++kt) {
        CP_WAIT1();
        __syncthreads();

        const int s = kt % NSTAGE;
        if (kt + 2 < KITERS) load_stage((kt + 2) % NSTAGE, kt + 2);
        CP_COMMIT();

        const uint32_t aS = smem_u32(Asm + s * STAGEW);
        const uint32_t bS = smem_u32(Bsm + s * STAGEW);

        #pragma unroll
        for (int ks = 0; ks < 2; ks++) {
            const int kw = ks * 8;
            uint32_t af[4][4], bf[4][2];
            #pragma unroll
            for (int mt = 0; mt < 4; mt++) {
                const int base = (wm * 64 + mt * 16) * SROWW + kw + aLane;
                ldsm_x4(af[mt], aS + base * 4);
            }
            #pragma unroll
            for (int np = 0; np < 2; np++) {
                uint32_t q[4];
                const int base = (wn * 32 + np * 16) * SROWW + kw + bLane;
                ldsm_x4(q, bS + base * 4);
                bf[2 * np + 0][0] = q[0]; bf[2 * np + 0][1] = q[1];
                bf[2 * np + 1][0] = q[2]; bf[2 * np + 1][1] = q[3];
            }
            #pragma unroll
            for (int mt = 0; mt < 4; mt++)
                #pragma unroll
                for (int nt = 0; nt < 4; nt++)
                    mma_f16(acc[mt][nt], af[mt], bf[nt]);
        }
    }

    #pragma unroll
    for (int mt = 0; mt < 4; mt++) {
        const int row = mb + wm * 64 + mt * 16 + gid;
        #pragma unroll
        for (int nt = 0; nt < 4; nt++) {
            const int col = nb + wn * 32 + nt * 8 + 2 * tig;
            const float b0 = bias[col], b1 = bias[col + 1];
            if constexpr (sizeof(OutT) == 4) {
                float2 v0 = make_float2(acc[mt][nt][0] + b0, acc[mt][nt][1] + b1);
                float2 v1 = make_float2(acc[mt][nt][2] + b0, acc[mt][nt][3] + b1);
                *reinterpret_cast<float2*>((float*)C + (size_t)row * Ntot + col)       = v0;
                *reinterpret_cast<float2*>((float*)C + (size_t)(row + 8) * Ntot + col) = v1;
            } else {
                __half2 h0 = __floats2half2_rn(acc[mt][nt][0] + b0, acc[mt][nt][1] + b1);
                __half2 h1 = __floats2half2_rn(acc[mt][nt][2] + b0, acc[mt][nt][3] + b1);
                *reinterpret_cast<__half2*>((__half*)C + (size_t)row * Ntot + col)       = h0;
                *reinterpret_cast<__half2*>((__half*)C + (size_t)(row + 8) * Ntot + col) = h1;
            }
        }
    }
}

// ---------------------------------------------------------------------------
// fp32 -> fp16 conversion pass
// ---------------------------------------------------------------------------
__global__ void f2h_kernel(const float4* __restrict__ in,
                           uint2* __restrict__ out, int n4) {
    int i = blockIdx.x * blockDim.x + threadIdx.x;
    if (i < n4) {
        float4 v = in[i];
        __half2 h0 = __floats2half2_rn(v.x, v.y);
        __half2 h1 = __floats2half2_rn(v.z, v.w);
        uint2 u;
        u.x = *reinterpret_cast<uint32_t*>(&h0);
        u.y = *reinterpret_cast<uint32_t*>(&h1);
        out[i] = u;
    }
}

// ---------------------------------------------------------------------------
// Window attention: one CTA per (window, head). fp16 smem operands, fp32 math.
// ---------------------------------------------------------------------------
#define SP   52    // St stride (floats)
#define SPH  56    // qt/kt stride (halves)
#define VPH  40    // vs stride (halves)

__global__ __launch_bounds__(192, 5)
void win_attn_kernel(const __half* __restrict__ qkv,
                     const float* __restrict__ mask,
                     const float* __restrict__ rpb,
                     const int*   __restrict__ rel_idx,
                     __half* __restrict__ attout) {
    const int w = blockIdx.x / NHEADS;
    const int h = blockIdx.x % NHEADS;
    const int tid = threadIdx.x;

    __shared__ __half qt[HD][SPH];        // qt[d][i] (unscaled)
    __shared__ __half kt[HD][SPH];        // kt[d][j]
    __shared__ __half vs[NTOK][VPH];      // v row-major
    __shared__ float  St[SP][SP];         // scores transposed St[j][i]

    // ---- Load: 3 * 49 rows * 4 granules (8 halves) = 588 ----
    const __half* base = qkv + (size_t)w * NTOK * QKV_N + h * HD;
    for (int idx = tid; idx < 3 * NTOK * 4; idx += 192) {
        const int m  = idx / (NTOK * 4);
        const int g  = idx - m * (NTOK * 4);
        const int i  = g >> 2;
        const int d8 = (g & 3) * 8;
        uint4 raw = *reinterpret_cast<const uint4*>(base + (size_t)i * QKV_N + m * DIM + d8);
        if (m == 2) {
            *reinterpret_cast<uint4*>(&vs[i][d8]) = raw;
        } else {
            const __half* hv = reinterpret_cast<const __half*>(&raw);
            __half (*dst)[SPH] = (m == 0) ? qt : kt;
            #pragma unroll
            for (int t = 0; t < 8; t++) dst[d8 + t][i] = hv[t];
        }
    }
    __syncthreads();

    // ---- Scores: 4x4 tile per thread, 169 threads ----
    if (tid < 169) {
        const int ti = tid % 13;
        const int tj = tid / 13;
        const int i0 = ti * 4;
        const int j0 = tj * 4;
        float acc[4][4];
        #pragma unroll
        for (int a = 0; a < 4; a++)
            #pragma unroll
            for (int b = 0; b < 4; b++) acc[a][b] = 0.0f;

        #pragma unroll
        for (int d = 0; d < HD; d++) {
            uint2 qr = *reinterpret_cast<const uint2*>(&qt[d][i0]);
            uint2 kr = *reinterpret_cast<const uint2*>(&kt[d][j0]);
            float2 q01 = __half22float2(*reinterpret_cast<__half2*>(&qr.x));
            float2 q23 = __half22float2(*reinterpret_cast<__half2*>(&qr.y));
            float2 k01 = __half22float2(*reinterpret_cast<__half2*>(&kr.x));
            float2 k23 = __half22float2(*reinterpret_cast<__half2*>(&kr.y));
            const float qa[4] = {q01.x, q01.y, q23.x, q23.y};
            const float ka[4] = {k01.x, k01.y, k23.x, k23.y};
            #pragma unroll
            for (int jj = 0; jj < 4; jj++)
                #pragma unroll
                for (int ii = 0; ii < 4; ii++)
                    acc[jj][ii] = fmaf(ka[jj], qa[ii], acc[jj][ii]);
        }

        const float* mrow = mask + (size_t)(w % NMASK) * NTOK * NTOK;
        #pragma unroll
        for (int jj = 0; jj < 4; jj++) {
            const int j = j0 + jj;
            #pragma unroll
            for (int ii = 0; ii < 4; ii++) {
                const int i = i0 + ii;
                if (i < NTOK && j < NTOK) {
                    const int e = i * NTOK + j;
                    St[j][i] = fmaf(acc[jj][ii], ATTN_SCALE,
                                    rpb[rel_idx[e] * NHEADS + h] + mrow[e]);
                }
            }
        }
    }
    __syncthreads();

    // ---- Softmax down columns of St (thread i) ----
    if (tid < NTOK) {
        const int i = tid;
        float m0 = -1e30f, m1 = -1e30f, m2 = -1e30f, m3 = -1e30f;
        #pragma unroll
        for (int j = 0; j < 48; j += 4) {
            m0 = fmaxf(m0, St[j + 0][i]);
            m1 = fmaxf(m1, St[j + 1][i]);
            m2 = fmaxf(m2, St[j + 2][i]);
            m3 = fmaxf(m3, St[j + 3][i]);
        }
        float m = fmaxf(fmaxf(m0, m1), fmaxf(fmaxf(m2, m3), St[48][i]));
        float s0 = 0.f, s1 = 0.f, s2 = 0.f, s3 = 0.f;
        #pragma unroll
        for (int j = 0; j < 48; j += 4) {
            float e0 = __expf(St[j + 0][i] - m);
            float e1 = __expf(St[j + 1][i] - m);
            float e2 = __expf(St[j + 2][i] - m);
            float e3 = __expf(St[j + 3][i] - m);
            St[j + 0][i] = e0; St[j + 1][i] = e1;
            St[j + 2][i] = e2; St[j + 3][i] = e3;
            s0 += e0; s1 += e1; s2 += e2; s3 += e3;
        }
        float el = __expf(St[48][i] - m);
        St[48][i] = el;
        const float inv = 1.0f / (s0 + s1 + s2 + s3 + el);
        #pragma unroll
        for (int j = 0; j < NTOK; j++) St[j][i] *= inv;
    }
    __syncthreads();

    // ---- PV: 4x4 tile per thread (i x d), 104 threads ----
    if (tid < 104) {
        const int ti = tid % 13;
        const int td = tid / 13;
        const int i0 = ti * 4;
        const int d0 = td * 4;
        float acc[4][4];
        #pragma unroll
        for (int a = 0; a < 4; a++)
            #pragma unroll
            for (int b = 0; b < 4; b++) acc[a][b] = 0.0f;

        for (int j = 0; j < NTOK; j++) {
            float4 pv = *reinterpret_cast<const float4*>(&St[j][i0]);
            uint2 vr = *reinterpret_cast<const uint2*>(&vs[j][d0]);
            float2 v01 = __half22float2(*reinterpret_cast<__half2*>(&vr.x));
            float2 v23 = __half22float2(*reinterpret_cast<__half2*>(&vr.y));
            const float pa[4] = {pv.x, pv.y, pv.z, pv.w};
            const float va[4] = {v01.x, v01.y, v23.x, v23.y};
            #pragma unroll
            for (int ii = 0; ii < 4; ii++)
                #pragma unroll
                for (int dd = 0; dd < 4; dd++)
                    acc[ii][dd] = fmaf(pa[ii], va[dd], acc[ii][dd]);
        }

        __half* obase = attout + (size_t)w * NTOK * DIM + h * HD;
        #pragma unroll
        for (int ii = 0; ii < 4; ii++) {
            const int i = i0 + ii;
            if (i < NTOK) {
                __half2 p0 = __floats2half2_rn(acc[ii][0], acc[ii][1]);
                __half2 p1 = __floats2half2_rn(acc[ii][2], acc[ii][3]);
                uint2 u;
                u.x = *reinterpret_cast<uint32_t*>(&p0);
                u.y = *reinterpret_cast<uint32_t*>(&p1);
                *reinterpret_cast<uint2*>(obase + (size_t)i * DIM + d0) = u;
            }
        }
    }
}

// ---------------------------------------------------------------------------
// Launch
// ---------------------------------------------------------------------------
extern "C" void kernel_launch(void* const* d_in, const int* in_sizes, int n_in,
                              void* d_out, int out_size) {
    const float* x      = (const float*)d_in[0];
    const float* mask   = (const float*)d_in[1];
    const float* rpb    = (const float*)d_in[2];
    const float* qkv_w  = (const float*)d_in[3];
    const float* qkv_b  = (const float*)d_in[4];
    const float* proj_w = (const float*)d_in[5];
    const float* proj_b = (const float*)d_in[6];
    const int*   rel_i  = (const int*)d_in[7];
    float* out = (float*)d_out;

    __half *qkvh, *xh, *ah, *wqh, *wph;
    cudaGetSymbolAddress((void**)&qkvh, g_qkvh);
    cudaGetSymbolAddress((void**)&xh,  g_xh);
    cudaGetSymbolAddress((void**)&ah,  g_ah);
    cudaGetSymbolAddress((void**)&wqh, g_wqh);
    cudaGetSymbolAddress((void**)&wph, g_wph);

    cudaFuncSetAttribute(gemm_mma_kernel<__half>,
                         cudaFuncAttributeMaxDynamicSharedMemorySize, SMEM_TOT);
    cudaFuncSetAttribute(gemm_mma_kernel<float>,
                         cudaFuncAttributeMaxDynamicSharedMemorySize, SMEM_TOT);

    // fp32 -> fp16 conversions
    {
        int n4 = (M_TOTAL * DIM) / 4;
        f2h_kernel<<<(n4 + 255) / 256, 256>>>((const float4*)x, (uint2*)xh, n4);
        int w4 = (QKV_N * DIM) / 4;
        f2h_kernel<<<(w4 + 255) / 256, 256>>>((const float4*)qkv_w, (uint2*)wqh, w4);
        int p4 = (DIM * DIM) / 4;
        f2h_kernel<<<(p4 + 255) / 256, 256>>>((const float4*)proj_w, (uint2*)wph, p4);
    }

    // 1) QKV projection -> fp16 qkv
    {
        dim3 grid(QKV_N / 128, M_TOTAL / 128);
        gemm_mma_kernel<__half><<<grid, 256, SMEM_TOT>>>(xh, wqh, qkv_b, qkvh, QKV_N);
    }

    // 2) Windowed attention (fp16 operands, fp32 math, fp16 out)
    win_attn_kernel<<<NWIN * NHEADS, 192>>>(qkvh, mask, rpb, rel_i, ah);

    // 3) Output projection -> fp32 d_out
    {
        dim3 grid(DIM / 128, M_TOTAL / 128);
        gemm_mma_kernel<float><<<grid, 256, SMEM_TOT>>>(ah, wph, proj_b, out, DIM);
    }
}

// round 7
// speedup vs baseline: 5.2854x; 1.1534x over previous
#include <cuda_runtime.h>
#include <cuda_fp16.h>
#include <cstdint>
#include <math.h>

// ---------------------------------------------------------------------------
// Problem constants
// ---------------------------------------------------------------------------
#define NTOK      49
#define DIM       384
#define NHEADS    12
#define HD        32
#define NWIN      4096
#define NMASK     1024
#define M_TOTAL   (NWIN * NTOK)     // 200704
#define QKV_N     (3 * DIM)         // 1152
#define KTOT      384
#define ATTN_SCALE 0.17677669529663687f

// Scratch (__device__ globals; allocation-free rule)
__device__ __align__(128) __half g_qkvh[(size_t)M_TOTAL * QKV_N];
__device__ __align__(128) __half g_xh [(size_t)M_TOTAL * DIM];
__device__ __align__(128) __half g_ah [(size_t)M_TOTAL * DIM];
__device__ __align__(128) __half g_wqh[QKV_N * DIM];
__device__ __align__(128) __half g_wph[DIM * DIM];
__device__ __align__(128) float  g_bias[NHEADS * NTOK * NTOK];   // rpb gathered per head

// ---------------------------------------------------------------------------
// Helpers
// ---------------------------------------------------------------------------
__device__ __forceinline__ uint32_t smem_u32(const void* p) {
    uint32_t a;
    asm("{ .reg .u64 t; cvta.to.shared.u64 t, %1; cvt.u32.u64 %0, t; }" : "=r"(a) : "l"(p));
    return a;
}

__device__ __forceinline__ void cpa16(uint32_t dst, const void* src) {
    asm volatile("cp.async.cg.shared.global [%0], [%1], 16;" :: "r"(dst), "l"(src) : "memory");
}
#define CP_COMMIT() asm volatile("cp.async.commit_group;" ::: "memory")
#define CP_WAIT1()  asm volatile("cp.async.wait_group 1;" ::: "memory")

__device__ __forceinline__ void mma_f16(float* d, const uint32_t* a, const uint32_t* b) {
    asm volatile(
        "mma.sync.aligned.m16n8k16.row.col.f32.f16.f16.f32 "
        "{%0,%1,%2,%3}, {%4,%5,%6,%7}, {%8,%9}, {%0,%1,%2,%3};"
        : "+f"(d[0]), "+f"(d[1]), "+f"(d[2]), "+f"(d[3])
        : "r"(a[0]), "r"(a[1]), "r"(a[2]), "r"(a[3]), "r"(b[0]), "r"(b[1]));
}

__device__ __forceinline__ void ldsm_x4(uint32_t* r, uint32_t addr) {
    asm volatile("ldmatrix.sync.aligned.m8n8.x4.shared.b16 {%0,%1,%2,%3}, [%4];"
                 : "=r"(r[0]), "=r"(r[1]), "=r"(r[2]), "=r"(r[3]) : "r"(addr));
}
__device__ __forceinline__ void ldsm_x4_t(uint32_t* r, uint32_t addr) {
    asm volatile("ldmatrix.sync.aligned.m8n8.x4.trans.shared.b16 {%0,%1,%2,%3}, [%4];"
                 : "=r"(r[0]), "=r"(r[1]), "=r"(r[2]), "=r"(r[3]) : "r"(addr));
}

// ---------------------------------------------------------------------------
// fp16 tensor-core GEMM (unchanged from r6)
// ---------------------------------------------------------------------------
#define BKH      32
#define NSTAGE   3
#define KITERS   (KTOT / BKH)
#define SROWW    20
#define STAGEW   (128 * SROWW)
#define SMEM_TOT (NSTAGE * STAGEW * 2 * 4)

template <typename OutT>
__global__ __launch_bounds__(256, 2)
void gemm_mma_kernel(const __half* __restrict__ A,
                     const __half* __restrict__ W,
                     const float* __restrict__ bias,
                     OutT* __restrict__ C,
                     int Ntot) {
    extern __shared__ __align__(16) uint32_t sm[];
    uint32_t* Asm = sm;
    uint32_t* Bsm = sm + NSTAGE * STAGEW;

    const int tid  = threadIdx.x;
    const int warp = tid >> 5;
    const int lane = tid & 31;
    const int gid  = lane >> 2;
    const int tig  = lane & 3;
    const int wm   = warp & 1;
    const int wn   = warp >> 1;
    const int mb   = blockIdx.y * 128;
    const int nb   = blockIdx.x * 128;

    const int aLane = ((lane & 7) + 8 * ((lane >> 3) & 1)) * SROWW + 4 * (lane >> 4);
    const int bLane = ((lane & 7) + 8 * (lane >> 4)) * SROWW + 4 * ((lane >> 3) & 1);

    auto load_stage = [&](int s, int kt) {
        uint32_t* as = Asm + s * STAGEW;
        uint32_t* bs = Bsm + s * STAGEW;
        const int k0 = kt * BKH;
        #pragma unroll
        for (int i = 0; i < 2; i++) {
            const int f = tid + i * 256;
            const int m = f >> 2;
            const int g = f & 3;
            cpa16(smem_u32(as + m * SROWW + g * 4), A + (size_t)(mb + m) * KTOT + k0 + g * 8);
            cpa16(smem_u32(bs + m * SROWW + g * 4), W + (size_t)(nb + m) * KTOT + k0 + g * 8);
        }
    };

    float acc[4][4][4];
    #pragma unroll
    for (int mt = 0; mt < 4; mt++)
        #pragma unroll
        for (int nt = 0; nt < 4; nt++)
            #pragma unroll
            for (int r = 0; r < 4; r++) acc[mt][nt][r] = 0.0f;

    load_stage(0, 0); CP_COMMIT();
    load_stage(1, 1); CP_COMMIT();

    for (int kt = 0; kt < KITERS; ++kt) {
        CP_WAIT1();
        __syncthreads();

        const int s = kt % NSTAGE;
        if (kt + 2 < KITERS) load_stage((kt + 2) % NSTAGE, kt + 2);
        CP_COMMIT();

        const uint32_t aS = smem_u32(Asm + s * STAGEW);
        const uint32_t bS = smem_u32(Bsm + s * STAGEW);

        #pragma unroll
        for (int ks = 0; ks < 2; ks++) {
            const int kw = ks * 8;
            uint32_t af[4][4], bf[4][2];
            #pragma unroll
            for (int mt = 0; mt < 4; mt++) {
                const int base = (wm * 64 + mt * 16) * SROWW + kw + aLane;
                ldsm_x4(af[mt], aS + base * 4);
            }
            #pragma unroll
            for (int np = 0; np < 2; np++) {
                uint32_t q[4];
                const int base = (wn * 32 + np * 16) * SROWW + kw + bLane;
                ldsm_x4(q, bS + base * 4);
                bf[2 * np + 0][0] = q[0]; bf[2 * np + 0][1] = q[1];
                bf[2 * np + 1][0] = q[2]; bf[2 * np + 1][1] = q[3];
            }
            #pragma unroll
            for (int mt = 0; mt < 4; mt++)
                #pragma unroll
                for (int nt = 0; nt < 4; nt++)
                    mma_f16(acc[mt][nt], af[mt], bf[nt]);
        }
    }

    #pragma unroll
    for (int mt = 0; mt < 4; mt++) {
        const int row = mb + wm * 64 + mt * 16 + gid;
        #pragma unroll
        for (int nt = 0; nt < 4; nt++) {
            const int col = nb + wn * 32 + nt * 8 + 2 * tig;
            const float b0 = bias[col], b1 = bias[col + 1];
            if constexpr (sizeof(OutT) == 4) {
                float2 v0 = make_float2(acc[mt][nt][0] + b0, acc[mt][nt][1] + b1);
                float2 v1 = make_float2(acc[mt][nt][2] + b0, acc[mt][nt][3] + b1);
                *reinterpret_cast<float2*>((float*)C + (size_t)row * Ntot + col)       = v0;
                *reinterpret_cast<float2*>((float*)C + (size_t)(row + 8) * Ntot + col) = v1;
            } else {
                __half2 h0 = __floats2half2_rn(acc[mt][nt][0] + b0, acc[mt][nt][1] + b1);
                __half2 h1 = __floats2half2_rn(acc[mt][nt][2] + b0, acc[mt][nt][3] + b1);
                *reinterpret_cast<__half2*>((__half*)C + (size_t)row * Ntot + col)       = h0;
                *reinterpret_cast<__half2*>((__half*)C + (size_t)(row + 8) * Ntot + col) = h1;
            }
        }
    }
}

// ---------------------------------------------------------------------------
// fp32 -> fp16 conversion; bias gather precompute
// ---------------------------------------------------------------------------
__global__ void f2h_kernel(const float4* __restrict__ in,
                           uint2* __restrict__ out, int n4) {
    int i = blockIdx.x * blockDim.x + threadIdx.x;
    if (i < n4) {
        float4 v = in[i];
        __half2 h0 = __floats2half2_rn(v.x, v.y);
        __half2 h1 = __floats2half2_rn(v.z, v.w);
        uint2 u;
        u.x = *reinterpret_cast<uint32_t*>(&h0);
        u.y = *reinterpret_cast<uint32_t*>(&h1);
        out[i] = u;
    }
}

__global__ void bias_prep_kernel(const float* __restrict__ rpb,
                                 const int* __restrict__ rel_idx,
                                 float* __restrict__ out) {
    int e = blockIdx.x * blockDim.x + threadIdx.x;
    if (e < NTOK * NTOK) {
        const int r = rel_idx[e];
        #pragma unroll
        for (int h = 0; h < NHEADS; h++)
            out[h * NTOK * NTOK + e] = rpb[r * NHEADS + h];
    }
}

// ---------------------------------------------------------------------------
// Window attention v3: tensor-core scores + PV. One CTA (128 thr) per (w,h).
// ---------------------------------------------------------------------------
#define QKV_STR  40    // halves (20 words)
#define S_STR    57    // floats
#define P_STR    72    // halves (36 words)

__global__ __launch_bounds__(128, 5)
void win_attn_kernel(const __half* __restrict__ qkv,
                     const float* __restrict__ mask,
                     const float* __restrict__ bias12,
                     __half* __restrict__ attout) {
    const int w = blockIdx.x / NHEADS;
    const int h = blockIdx.x % NHEADS;
    const int tid  = threadIdx.x;
    const int warp = tid >> 5;
    const int lane = tid & 31;
    const int gid  = lane >> 2;
    const int tig  = lane & 3;

    __shared__ __align__(16) __half Qh[64][QKV_STR];
    __shared__ __align__(16) __half Kh[64][QKV_STR];
    __shared__ __align__(16) __half Vh[64][QKV_STR];
    __shared__ __align__(16) float  Sf[NTOK][S_STR];
    __shared__ __align__(16) __half Ph[64][P_STR];

    // ---- Zero pads: all of Ph; rows 49..63 of Qh/Kh/Vh ----
    const uint4 z4 = make_uint4(0, 0, 0, 0);
    for (int idx = tid; idx < 576; idx += 128)
        reinterpret_cast<uint4*>(&Ph[0][0])[idx] = z4;
    for (int idx = tid; idx < 225; idx += 128) {
        const int a = idx / 75;
        const int rem = idx - a * 75;
        const int r = 49 + rem / 5;
        const int g = rem % 5;
        __half* dst = (a == 0) ? &Qh[r][0] : (a == 1) ? &Kh[r][0] : &Vh[r][0];
        reinterpret_cast<uint4*>(dst)[g] = z4;
    }

    // ---- Load q/k/v rows (row-major fp16) ----
    const __half* base = qkv + (size_t)w * NTOK * QKV_N + h * HD;
    for (int idx = tid; idx < 3 * NTOK * 4; idx += 128) {
        const int m = idx / (NTOK * 4);
        const int rem = idx - m * (NTOK * 4);
        const int i = rem >> 2;
        const int g = rem & 3;
        uint4 v = *reinterpret_cast<const uint4*>(base + (size_t)i * QKV_N + m * DIM + g * 8);
        __half* dst = (m == 0) ? &Qh[i][0] : (m == 1) ? &Kh[i][0] : &Vh[i][0];
        reinterpret_cast<uint4*>(dst)[g] = v;
    }
    __syncthreads();

    // ---- Scores: S = Q K^T (rows warp*16..+16, cols 0..63) ----
    const uint32_t QS = smem_u32(&Qh[0][0]);
    const uint32_t KS = smem_u32(&Kh[0][0]);
    const int aL = ((lane & 7) + 8 * ((lane >> 3) & 1)) * 20 + 4 * (lane >> 4);
    const int bL = ((lane & 7) + 8 * (lane >> 4)) * 20 + 4 * ((lane >> 3) & 1);

    float acc[8][4];
    #pragma unroll
    for (int a = 0; a < 8; a++)
        #pragma unroll
        for (int r = 0; r < 4; r++) acc[a][r] = 0.0f;

    #pragma unroll
    for (int ks = 0; ks < 2; ks++) {
        uint32_t af[4];
        ldsm_x4(af, QS + (uint32_t)(warp * 16 * 20 + ks * 8 + aL) * 4);
        #pragma unroll
        for (int nb = 0; nb < 4; nb++) {
            uint32_t q[4];
            ldsm_x4(q, KS + (uint32_t)(nb * 16 * 20 + ks * 8 + bL) * 4);
            mma_f16(acc[nb * 2 + 0], af, q + 0);
            mma_f16(acc[nb * 2 + 1], af, q + 2);
        }
    }

    // store scores + scale + bias + mask (only i<49, j<49)
    {
        const float* mrow = mask + (size_t)(w % NMASK) * NTOK * NTOK;
        const float* brow = bias12 + h * NTOK * NTOK;
        const int i0 = warp * 16 + gid;
        #pragma unroll
        for (int nt = 0; nt < 8; nt++) {
            const int j = nt * 8 + 2 * tig;
            if (j < NTOK) {
                #pragma unroll
                for (int rr = 0; rr < 2; rr++) {
                    const int i = i0 + rr * 8;
                    if (i < NTOK) {
                        const int e = i * NTOK + j;
                        Sf[i][j] = fmaf(acc[nt][rr * 2], ATTN_SCALE, brow[e] + mrow[e]);
                        if (j + 1 < NTOK)
                            Sf[i][j + 1] = fmaf(acc[nt][rr * 2 + 1], ATTN_SCALE,
                                                brow[e + 1] + mrow[e + 1]);
                    }
                }
            }
        }
    }
    __syncthreads();

    // ---- Row softmax (threads 0..48), P -> fp16 into Ph ----
    if (tid < NTOK) {
        const int i = tid;
        float m = -1e30f;
        #pragma unroll 7
        for (int j = 0; j < NTOK; j++) m = fmaxf(m, Sf[i][j]);
        float s = 0.0f;
        #pragma unroll 7
        for (int j = 0; j < NTOK; j++) {
            const float e = __expf(Sf[i][j] - m);
            Sf[i][j] = e;
            s += e;
        }
        const float inv = 1.0f / s;
        #pragma unroll 7
        for (int j = 0; j < NTOK; j++)
            Ph[i][j] = __float2half_rn(Sf[i][j] * inv);
    }
    __syncthreads();

    // ---- PV: O = P V (rows warp*16..+16, d 0..31) ----
    const uint32_t PS = smem_u32(&Ph[0][0]);
    const uint32_t VS = smem_u32(&Vh[0][0]);
    const int aLp = ((lane & 7) + 8 * ((lane >> 3) & 1)) * 36 + 4 * (lane >> 4);
    const int vL  = ((lane & 7) + 8 * ((lane >> 3) & 1)) * 20 + 4 * (lane >> 4);

    float pacc[4][4];
    #pragma unroll
    for (int a = 0; a < 4; a++)
        #pragma unroll
        for (int r = 0; r < 4; r++) pacc[a][r] = 0.0f;

    #pragma unroll
    for (int ks = 0; ks < 4; ks++) {
        uint32_t pf[4];
        ldsm_x4(pf, PS + (uint32_t)(warp * 16 * 36 + ks * 8 + aLp) * 4);
        uint32_t v0[4], v1[4];
        ldsm_x4_t(v0, VS + (uint32_t)(ks * 16 * 20 + vL) * 4);
        ldsm_x4_t(v1, VS + (uint32_t)(ks * 16 * 20 + 8 + vL) * 4);
        mma_f16(pacc[0], pf, v0 + 0);
        mma_f16(pacc[1], pf, v0 + 2);
        mma_f16(pacc[2], pf, v1 + 0);
        mma_f16(pacc[3], pf, v1 + 2);
    }

    // ---- Store O (fp16) ----
    {
        __half* ob = attout + (size_t)w * NTOK * DIM + h * HD;
        const int i0 = warp * 16 + gid;
        #pragma unroll
        for (int nt = 0; nt < 4; nt++) {
            const int d = nt * 8 + 2 * tig;
            #pragma unroll
            for (int rr = 0; rr < 2; rr++) {
                const int i = i0 + rr * 8;
                if (i < NTOK) {
                    __half2 hv = __floats2half2_rn(pacc[nt][rr * 2], pacc[nt][rr * 2 + 1]);
                    *reinterpret_cast<__half2*>(ob + (size_t)i * DIM + d) = hv;
                }
            }
        }
    }
}

// ---------------------------------------------------------------------------
// Launch
// ---------------------------------------------------------------------------
extern "C" void kernel_launch(void* const* d_in, const int* in_sizes, int n_in,
                              void* d_out, int out_size) {
    const float* x      = (const float*)d_in[0];
    const float* mask   = (const float*)d_in[1];
    const float* rpb    = (const float*)d_in[2];
    const float* qkv_w  = (const float*)d_in[3];
    const float* qkv_b  = (const float*)d_in[4];
    const float* proj_w = (const float*)d_in[5];
    const float* proj_b = (const float*)d_in[6];
    const int*   rel_i  = (const int*)d_in[7];
    float* out = (float*)d_out;

    __half *qkvh, *xh, *ah, *wqh, *wph;
    float* biasb;
    cudaGetSymbolAddress((void**)&qkvh, g_qkvh);
    cudaGetSymbolAddress((void**)&xh,  g_xh);
    cudaGetSymbolAddress((void**)&ah,  g_ah);
    cudaGetSymbolAddress((void**)&wqh, g_wqh);
    cudaGetSymbolAddress((void**)&wph, g_wph);
    cudaGetSymbolAddress((void**)&biasb, g_bias);

    cudaFuncSetAttribute(gemm_mma_kernel<__half>,
                         cudaFuncAttributeMaxDynamicSharedMemorySize, SMEM_TOT);
    cudaFuncSetAttribute(gemm_mma_kernel<float>,
                         cudaFuncAttributeMaxDynamicSharedMemorySize, SMEM_TOT);

    // conversions + bias gather
    {
        int n4 = (M_TOTAL * DIM) / 4;
        f2h_kernel<<<(n4 + 255) / 256, 256>>>((const float4*)x, (uint2*)xh, n4);
        int w4 = (QKV_N * DIM) / 4;
        f2h_kernel<<<(w4 + 255) / 256, 256>>>((const float4*)qkv_w, (uint2*)wqh, w4);
        int p4 = (DIM * DIM) / 4;
        f2h_kernel<<<(p4 + 255) / 256, 256>>>((const float4*)proj_w, (uint2*)wph, p4);
        bias_prep_kernel<<<(NTOK * NTOK + 127) / 128, 128>>>(rpb, rel_i, biasb);
    }

    // 1) QKV projection -> fp16 qkv
    {
        dim3 grid(QKV_N / 128, M_TOTAL / 128);
        gemm_mma_kernel<__half><<<grid, 256, SMEM_TOT>>>(xh, wqh, qkv_b, qkvh, QKV_N);
    }

    // 2) Windowed attention (tensor-core)
    win_attn_kernel<<<NWIN * NHEADS, 128>>>(qkvh, mask, biasb, ah);

    // 3) Output projection -> fp32 d_out
    {
        dim3 grid(DIM / 128, M_TOTAL / 128);
        gemm_mma_kernel<float><<<grid, 256, SMEM_TOT>>>(ah, wph, proj_b, out, DIM);
    }
}

// round 8
// speedup vs baseline: 5.8877x; 1.1140x over previous
#include <cuda_runtime.h>
#include <cuda_fp16.h>
#include <cstdint>
#include <math.h>

// ---------------------------------------------------------------------------
// Problem constants
// ---------------------------------------------------------------------------
#define NTOK      49
#define DIM       384
#define NHEADS    12
#define HD        32
#define NWIN      4096
#define NMASK     1024
#define M_TOTAL   (NWIN * NTOK)     // 200704
#define QKV_N     (3 * DIM)         // 1152
#define KTOT      384
#define ATTN_SCALE 0.17677669529663687f
#define BM_STR    2404              // padded bias+mask row (floats, 16B-aligned)

// Scratch (__device__ globals; allocation-free rule)
__device__ __align__(128) __half g_qkvh[(size_t)M_TOTAL * QKV_N];
__device__ __align__(128) __half g_xh [(size_t)M_TOTAL * DIM];
__device__ __align__(128) __half g_ah [(size_t)M_TOTAL * DIM];
__device__ __align__(128) __half g_wqh[QKV_N * DIM];
__device__ __align__(128) __half g_wph[DIM * DIM];
__device__ __align__(128) float  g_bm[(size_t)NMASK * NHEADS * BM_STR];  // bias+mask fused

// ---------------------------------------------------------------------------
// Helpers
// ---------------------------------------------------------------------------
__device__ __forceinline__ uint32_t smem_u32(const void* p) {
    uint32_t a;
    asm("{ .reg .u64 t; cvta.to.shared.u64 t, %1; cvt.u32.u64 %0, t; }" : "=r"(a) : "l"(p));
    return a;
}

__device__ __forceinline__ void cpa16(uint32_t dst, const void* src) {
    asm volatile("cp.async.cg.shared.global [%0], [%1], 16;" :: "r"(dst), "l"(src) : "memory");
}
#define CP_COMMIT() asm volatile("cp.async.commit_group;" ::: "memory")
#define CP_WAIT1()  asm volatile("cp.async.wait_group 1;" ::: "memory")
#define CP_WAIT0()  asm volatile("cp.async.wait_group 0;" ::: "memory")

__device__ __forceinline__ void mma_f16(float* d, const uint32_t* a, const uint32_t* b) {
    asm volatile(
        "mma.sync.aligned.m16n8k16.row.col.f32.f16.f16.f32 "
        "{%0,%1,%2,%3}, {%4,%5,%6,%7}, {%8,%9}, {%0,%1,%2,%3};"
        : "+f"(d[0]), "+f"(d[1]), "+f"(d[2]), "+f"(d[3])
        : "r"(a[0]), "r"(a[1]), "r"(a[2]), "r"(a[3]), "r"(b[0]), "r"(b[1]));
}

__device__ __forceinline__ void ldsm_x4(uint32_t* r, uint32_t addr) {
    asm volatile("ldmatrix.sync.aligned.m8n8.x4.shared.b16 {%0,%1,%2,%3}, [%4];"
                 : "=r"(r[0]), "=r"(r[1]), "=r"(r[2]), "=r"(r[3]) : "r"(addr));
}
__device__ __forceinline__ void ldsm_x4_t(uint32_t* r, uint32_t addr) {
    asm volatile("ldmatrix.sync.aligned.m8n8.x4.trans.shared.b16 {%0,%1,%2,%3}, [%4];"
                 : "=r"(r[0]), "=r"(r[1]), "=r"(r[2]), "=r"(r[3]) : "r"(addr));
}

// ---------------------------------------------------------------------------
// fp16 tensor-core GEMM (unchanged, proven)
// ---------------------------------------------------------------------------
#define BKH      32
#define NSTAGE   3
#define KITERS   (KTOT / BKH)
#define SROWW    20
#define STAGEW   (128 * SROWW)
#define SMEM_TOT (NSTAGE * STAGEW * 2 * 4)

template <typename OutT>
__global__ __launch_bounds__(256, 2)
void gemm_mma_kernel(const __half* __restrict__ A,
                     const __half* __restrict__ W,
                     const float* __restrict__ bias,
                     OutT* __restrict__ C,
                     int Ntot) {
    extern __shared__ __align__(16) uint32_t sm[];
    uint32_t* Asm = sm;
    uint32_t* Bsm = sm + NSTAGE * STAGEW;

    const int tid  = threadIdx.x;
    const int warp = tid >> 5;
    const int lane = tid & 31;
    const int gid  = lane >> 2;
    const int tig  = lane & 3;
    const int wm   = warp & 1;
    const int wn   = warp >> 1;
    const int mb   = blockIdx.y * 128;
    const int nb   = blockIdx.x * 128;

    const int aLane = ((lane & 7) + 8 * ((lane >> 3) & 1)) * SROWW + 4 * (lane >> 4);
    const int bLane = ((lane & 7) + 8 * (lane >> 4)) * SROWW + 4 * ((lane >> 3) & 1);

    auto load_stage = [&](int s, int kt) {
        uint32_t* as = Asm + s * STAGEW;
        uint32_t* bs = Bsm + s * STAGEW;
        const int k0 = kt * BKH;
        #pragma unroll
        for (int i = 0; i < 2; i++) {
            const int f = tid + i * 256;
            const int m = f >> 2;
            const int g = f & 3;
            cpa16(smem_u32(as + m * SROWW + g * 4), A + (size_t)(mb + m) * KTOT + k0 + g * 8);
            cpa16(smem_u32(bs + m * SROWW + g * 4), W + (size_t)(nb + m) * KTOT + k0 + g * 8);
        }
    };

    float acc[4][4][4];
    #pragma unroll
    for (int mt = 0; mt < 4; mt++)
        #pragma unroll
        for (int nt = 0; nt < 4; nt++)
            #pragma unroll
            for (int r = 0; r < 4; r++) acc[mt][nt][r] = 0.0f;

    load_stage(0, 0); CP_COMMIT();
    load_stage(1, 1); CP_COMMIT();

    for (int kt = 0; kt < KITERS; ++kt) {
        CP_WAIT1();
        __syncthreads();

        const int s = kt % NSTAGE;
        if (kt + 2 < KITERS) load_stage((kt + 2) % NSTAGE, kt + 2);
        CP_COMMIT();

        const uint32_t aS = smem_u32(Asm + s * STAGEW);
        const uint32_t bS = smem_u32(Bsm + s * STAGEW);

        #pragma unroll
        for (int ks = 0; ks < 2; ks++) {
            const int kw = ks * 8;
            uint32_t af[4][4], bf[4][2];
            #pragma unroll
            for (int mt = 0; mt < 4; mt++) {
                const int base = (wm * 64 + mt * 16) * SROWW + kw + aLane;
                ldsm_x4(af[mt], aS + base * 4);
            }
            #pragma unroll
            for (int np = 0; np < 2; np++) {
                uint32_t q[4];
                const int base = (wn * 32 + np * 16) * SROWW + kw + bLane;
                ldsm_x4(q, bS + base * 4);
                bf[2 * np + 0][0] = q[0]; bf[2 * np + 0][1] = q[1];
                bf[2 * np + 1][0] = q[2]; bf[2 * np + 1][1] = q[3];
            }
            #pragma unroll
            for (int mt = 0; mt < 4; mt++)
                #pragma unroll
                for (int nt = 0; nt < 4; nt++)
                    mma_f16(acc[mt][nt], af[mt], bf[nt]);
        }
    }

    #pragma unroll
    for (int mt = 0; mt < 4; mt++) {
        const int row = mb + wm * 64 + mt * 16 + gid;
        #pragma unroll
        for (int nt = 0; nt < 4; nt++) {
            const int col = nb + wn * 32 + nt * 8 + 2 * tig;
            const float b0 = bias[col], b1 = bias[col + 1];
            if constexpr (sizeof(OutT) == 4) {
                float2 v0 = make_float2(acc[mt][nt][0] + b0, acc[mt][nt][1] + b1);
                float2 v1 = make_float2(acc[mt][nt][2] + b0, acc[mt][nt][3] + b1);
                *reinterpret_cast<float2*>((float*)C + (size_t)row * Ntot + col)       = v0;
                *reinterpret_cast<float2*>((float*)C + (size_t)(row + 8) * Ntot + col) = v1;
            } else {
                __half2 h0 = __floats2half2_rn(acc[mt][nt][0] + b0, acc[mt][nt][1] + b1);
                __half2 h1 = __floats2half2_rn(acc[mt][nt][2] + b0, acc[mt][nt][3] + b1);
                *reinterpret_cast<__half2*>((__half*)C + (size_t)row * Ntot + col)       = h0;
                *reinterpret_cast<__half2*>((__half*)C + (size_t)(row + 8) * Ntot + col) = h1;
            }
        }
    }
}

// ---------------------------------------------------------------------------
// fp32 -> fp16 conversion; fused bias+mask precompute
// ---------------------------------------------------------------------------
__global__ void f2h_kernel(const float4* __restrict__ in,
                           uint2* __restrict__ out, int n4) {
    int i = blockIdx.x * blockDim.x + threadIdx.x;
    if (i < n4) {
        float4 v = in[i];
        __half2 h0 = __floats2half2_rn(v.x, v.y);
        __half2 h1 = __floats2half2_rn(v.z, v.w);
        uint2 u;
        u.x = *reinterpret_cast<uint32_t*>(&h0);
        u.y = *reinterpret_cast<uint32_t*>(&h1);
        out[i] = u;
    }
}

// out[(m*12+h)*BM_STR + e] = rpb[rel_idx[e]*12 + h] + mask[m*2401 + e]
__global__ void bm_prep_kernel(const float* __restrict__ rpb,
                               const int* __restrict__ rel_idx,
                               const float* __restrict__ mask,
                               float* __restrict__ out) {
    const int row = blockIdx.x;              // 0 .. NMASK*NHEADS-1  (m-major)
    const int m = row / NHEADS;
    const int h = row - m * NHEADS;
    const float* mrow = mask + (size_t)m * (NTOK * NTOK);
    float* orow = out + (size_t)row * BM_STR;
    for (int e = threadIdx.x; e < BM_STR; e += 128)
        orow[e] = (e < NTOK * NTOK) ? rpb[rel_idx[e] * NHEADS + h] + mrow[e] : 0.0f;
}

// ---------------------------------------------------------------------------
// Window attention v4: cp.async prefetch (qkv + fused bias/mask), tensor-core
// scores + PV, P aliases dead Q/K smem, fused pad-zeroing with softmax.
// ---------------------------------------------------------------------------
__global__ __launch_bounds__(128, 6)
void win_attn_kernel(const __half* __restrict__ qkv,
                     const float* __restrict__ bm,
                     __half* __restrict__ attout) {
    const int w = blockIdx.x / NHEADS;
    const int h = blockIdx.x % NHEADS;
    const int tid  = threadIdx.x;
    const int warp = tid >> 5;
    const int lane = tid & 31;
    const int gid  = lane >> 2;
    const int tig  = lane & 3;

    // Q/K region (10240 B) is reused for P (9216 B) after the score MMA.
    __shared__ __align__(16) char  ub[64 * 40 * 2 * 2];
    __shared__ __align__(16) __half Vh[64][40];
    __shared__ __align__(16) float  Sf[NTOK][57];
    __shared__ __align__(16) float  BMs[BM_STR];

    __half (*Qh)[40] = reinterpret_cast<__half(*)[40]>(ub);
    __half (*Kh)[40] = reinterpret_cast<__half(*)[40]>(ub + 64 * 40 * 2);
    __half (*Ph)[72] = reinterpret_cast<__half(*)[72]>(ub);

    // ---- Prefetch: qkv rows (588 x 16B) + bm row (601 x 16B) ----
    const __half* base = qkv + (size_t)w * NTOK * QKV_N + h * HD;
    for (int idx = tid; idx < 3 * NTOK * 4; idx += 128) {
        const int m = idx / (NTOK * 4);
        const int rem = idx - m * (NTOK * 4);
        const int i = rem >> 2;
        const int g = rem & 3;
        __half* dst = (m == 0) ? &Qh[i][0] : (m == 1) ? &Kh[i][0] : &Vh[i][0];
        cpa16(smem_u32(dst + g * 8), base + (size_t)i * QKV_N + m * DIM + g * 8);
    }
    {
        const float* bmrow = bm + (size_t)((w & (NMASK - 1)) * NHEADS + h) * BM_STR;
        for (int idx = tid; idx < BM_STR / 4; idx += 128)
            cpa16(smem_u32(&BMs[idx * 4]), bmrow + idx * 4);
    }
    CP_COMMIT();

    // ---- Zero pad rows 49..63 of Q/K/V while loads are in flight ----
    const uint4 z4 = make_uint4(0, 0, 0, 0);
    for (int idx = tid; idx < 225; idx += 128) {
        const int a = idx / 75;
        const int rem = idx - a * 75;
        const int r = 49 + rem / 5;
        const int g = rem % 5;
        __half* dst = (a == 0) ? &Qh[r][0] : (a == 1) ? &Kh[r][0] : &Vh[r][0];
        reinterpret_cast<uint4*>(dst)[g] = z4;
    }
    CP_WAIT0();
    __syncthreads();

    // ---- Scores: S = Q K^T ----
    const uint32_t QS = smem_u32(&Qh[0][0]);
    const uint32_t KS = smem_u32(&Kh[0][0]);
    const int aL = ((lane & 7) + 8 * ((lane >> 3) & 1)) * 20 + 4 * (lane >> 4);
    const int bL = ((lane & 7) + 8 * (lane >> 4)) * 20 + 4 * ((lane >> 3) & 1);

    float acc[8][4];
    #pragma unroll
    for (int a = 0; a < 8; a++)
        #pragma unroll
        for (int r = 0; r < 4; r++) acc[a][r] = 0.0f;

    #pragma unroll
    for (int ks = 0; ks < 2; ks++) {
        uint32_t af[4];
        ldsm_x4(af, QS + (uint32_t)(warp * 16 * 20 + ks * 8 + aL) * 4);
        #pragma unroll
        for (int nb = 0; nb < 4; nb++) {
            uint32_t q[4];
            ldsm_x4(q, KS + (uint32_t)(nb * 16 * 20 + ks * 8 + bL) * 4);
            mma_f16(acc[nb * 2 + 0], af, q + 0);
            mma_f16(acc[nb * 2 + 1], af, q + 2);
        }
    }

    // scores + scale + fused bias/mask from smem
    {
        const int i0 = warp * 16 + gid;
        #pragma unroll
        for (int nt = 0; nt < 8; nt++) {
            const int j = nt * 8 + 2 * tig;
            if (j < NTOK) {
                #pragma unroll
                for (int rr = 0; rr < 2; rr++) {
                    const int i = i0 + rr * 8;
                    if (i < NTOK) {
                        const int e = i * NTOK + j;
                        Sf[i][j] = fmaf(acc[nt][rr * 2], ATTN_SCALE, BMs[e]);
                        if (j + 1 < NTOK)
                            Sf[i][j + 1] = fmaf(acc[nt][rr * 2 + 1], ATTN_SCALE, BMs[e + 1]);
                    }
                }
            }
        }
    }
    __syncthreads();   // Sf complete; Q/K dead -> Ph region reusable

    // ---- Softmax rows (threads 0..48) || P pad-zeroing (threads 49..127) ----
    if (tid < NTOK) {
        const int i = tid;
        float m = -1e30f;
        #pragma unroll 7
        for (int j = 0; j < NTOK; j++) m = fmaxf(m, Sf[i][j]);
        float s = 0.0f;
        #pragma unroll 7
        for (int j = 0; j < NTOK; j++) {
            const float e = __expf(Sf[i][j] - m);
            Sf[i][j] = e;
            s += e;
        }
        const float inv = 1.0f / s;
        #pragma unroll 7
        for (int j = 0; j < NTOK; j++)
            Ph[i][j] = __float2half_rn(Sf[i][j] * inv);
        #pragma unroll
        for (int j = NTOK; j < 56; j++)
            Ph[i][j] = __ushort_as_half((unsigned short)0);
    } else {
        // rows 49..63 full (15*9=135 uint4) + rows 0..48 cols 56..71 (49*2=98)
        for (int idx = tid - NTOK; idx < 233; idx += 128 - NTOK) {
            int r, c;
            if (idx < 135) { r = 49 + idx / 9; c = (idx % 9) * 8; }
            else           { const int q = idx - 135; r = q >> 1; c = 56 + (q & 1) * 8; }
            *reinterpret_cast<uint4*>(&Ph[r][c]) = z4;
        }
    }
    __syncthreads();

    // ---- PV: O = P V ----
    const uint32_t PS = smem_u32(&Ph[0][0]);
    const uint32_t VS = smem_u32(&Vh[0][0]);
    const int aLp = ((lane & 7) + 8 * ((lane >> 3) & 1)) * 36 + 4 * (lane >> 4);
    const int vL  = ((lane & 7) + 8 * ((lane >> 3) & 1)) * 20 + 4 * (lane >> 4);

    float pacc[4][4];
    #pragma unroll
    for (int a = 0; a < 4; a++)
        #pragma unroll
        for (int r = 0; r < 4; r++) pacc[a][r] = 0.0f;

    #pragma unroll
    for (int ks = 0; ks < 4; ks++) {
        uint32_t pf[4];
        ldsm_x4(pf, PS + (uint32_t)(warp * 16 * 36 + ks * 8 + aLp) * 4);
        uint32_t v0[4], v1[4];
        ldsm_x4_t(v0, VS + (uint32_t)(ks * 16 * 20 + vL) * 4);
        ldsm_x4_t(v1, VS + (uint32_t)(ks * 16 * 20 + 8 + vL) * 4);
        mma_f16(pacc[0], pf, v0 + 0);
        mma_f16(pacc[1], pf, v0 + 2);
        mma_f16(pacc[2], pf, v1 + 0);
        mma_f16(pacc[3], pf, v1 + 2);
    }

    // ---- Store O (fp16) ----
    {
        __half* ob = attout + (size_t)w * NTOK * DIM + h * HD;
        const int i0 = warp * 16 + gid;
        #pragma unroll
        for (int nt = 0; nt < 4; nt++) {
            const int d = nt * 8 + 2 * tig;
            #pragma unroll
            for (int rr = 0; rr < 2; rr++) {
                const int i = i0 + rr * 8;
                if (i < NTOK) {
                    __half2 hv = __floats2half2_rn(pacc[nt][rr * 2], pacc[nt][rr * 2 + 1]);
                    *reinterpret_cast<__half2*>(ob + (size_t)i * DIM + d) = hv;
                }
            }
        }
    }
}

// ---------------------------------------------------------------------------
// Launch
// ---------------------------------------------------------------------------
extern "C" void kernel_launch(void* const* d_in, const int* in_sizes, int n_in,
                              void* d_out, int out_size) {
    const float* x      = (const float*)d_in[0];
    const float* mask   = (const float*)d_in[1];
    const float* rpb    = (const float*)d_in[2];
    const float* qkv_w  = (const float*)d_in[3];
    const float* qkv_b  = (const float*)d_in[4];
    const float* proj_w = (const float*)d_in[5];
    const float* proj_b = (const float*)d_in[6];
    const int*   rel_i  = (const int*)d_in[7];
    float* out = (float*)d_out;

    __half *qkvh, *xh, *ah, *wqh, *wph;
    float* bmb;
    cudaGetSymbolAddress((void**)&qkvh, g_qkvh);
    cudaGetSymbolAddress((void**)&xh,  g_xh);
    cudaGetSymbolAddress((void**)&ah,  g_ah);
    cudaGetSymbolAddress((void**)&wqh, g_wqh);
    cudaGetSymbolAddress((void**)&wph, g_wph);
    cudaGetSymbolAddress((void**)&bmb, g_bm);

    cudaFuncSetAttribute(gemm_mma_kernel<__half>,
                         cudaFuncAttributeMaxDynamicSharedMemorySize, SMEM_TOT);
    cudaFuncSetAttribute(gemm_mma_kernel<float>,
                         cudaFuncAttributeMaxDynamicSharedMemorySize, SMEM_TOT);

    // conversions + fused bias/mask precompute
    {
        int n4 = (M_TOTAL * DIM) / 4;
        f2h_kernel<<<(n4 + 255) / 256, 256>>>((const float4*)x, (uint2*)xh, n4);
        int w4 = (QKV_N * DIM) / 4;
        f2h_kernel<<<(w4 + 255) / 256, 256>>>((const float4*)qkv_w, (uint2*)wqh, w4);
        int p4 = (DIM * DIM) / 4;
        f2h_kernel<<<(p4 + 255) / 256, 256>>>((const float4*)proj_w, (uint2*)wph, p4);
        bm_prep_kernel<<<NMASK * NHEADS, 128>>>(rpb, rel_i, mask, bmb);
    }

    // 1) QKV projection -> fp16 qkv
    {
        dim3 grid(QKV_N / 128, M_TOTAL / 128);
        gemm_mma_kernel<__half><<<grid, 256, SMEM_TOT>>>(xh, wqh, qkv_b, qkvh, QKV_N);
    }

    // 2) Windowed attention (tensor-core, prefetched operands)
    win_attn_kernel<<<NWIN * NHEADS, 128>>>(qkvh, bmb, ah);

    // 3) Output projection -> fp32 d_out
    {
        dim3 grid(DIM / 128, M_TOTAL / 128);
        gemm_mma_kernel<float><<<grid, 256, SMEM_TOT>>>(ah, wph, proj_b, out, DIM);
    }
}